// round 5
// baseline (speedup 1.0000x reference)
#include <cuda_runtime.h>
#include <math.h>

#define D_MODEL 1024
#define S_LEN   1024
#define BATCH   4
#define NTOK    4096
#define NHEADS  16
#define HD      64
#define NRULES  64
#define RANK    8
#define SRANK   32
#define NBLK    16
#define TOPK    32
#define KSPLIT  4

#define NEGINF (__int_as_float(0xff800000))

// ---------------- scratch (device globals; no allocation allowed) ------------
__device__ float g_T1[3 * NTOK * SRANK];
__device__ float g_P [KSPLIT * 3 * NTOK * SRANK];
__device__ float g_Q [NTOK * D_MODEL];
__device__ float g_K [NTOK * D_MODEL];
__device__ float g_V [NTOK * D_MODEL];
__device__ float g_AO[NTOK * D_MODEL];
__device__ float g_A [NRULES * NRULES];
__device__ unsigned long long g_allow[NTOK];
__device__ float2 g_rope[S_LEN * 32];

__device__ __forceinline__ unsigned f2tf(float x) {
    unsigned u;
    asm("cvt.rna.tf32.f32 %0, %1;" : "=r"(u) : "f"(x));
    return u;
}

__device__ __forceinline__ void mma_tf32(float d[4], const unsigned a[4],
                                         unsigned b0, unsigned b1) {
    asm volatile(
        "mma.sync.aligned.m16n8k8.row.col.f32.tf32.tf32.f32 "
        "{%0,%1,%2,%3}, {%4,%5,%6,%7}, {%8,%9}, {%0,%1,%2,%3};\n"
        : "+f"(d[0]), "+f"(d[1]), "+f"(d[2]), "+f"(d[3])
        : "r"(a[0]), "r"(a[1]), "r"(a[2]), "r"(a[3]), "r"(b0), "r"(b1));
}

__device__ __forceinline__ void cp16(float* smem_dst, const float* gsrc) {
    unsigned s = (unsigned)__cvta_generic_to_shared(smem_dst);
    asm volatile("cp.async.cg.shared.global [%0], [%1], 16;" :: "r"(s), "l"(gsrc));
}
__device__ __forceinline__ void cp_commit() {
    asm volatile("cp.async.commit_group;");
}
template <int N>
__device__ __forceinline__ void cp_wait() {
    asm volatile("cp.async.wait_group %0;" :: "n"(N));
}

// ---------------- affinity table ---------------------------------------------
__global__ void aff_kernel(const float* __restrict__ rq, const float* __restrict__ rk,
                           float* __restrict__ A) {
    int idx = blockIdx.x * blockDim.x + threadIdx.x;
    if (idx >= NRULES * NRULES) return;
    int i = idx >> 6, j = idx & 63;
    float qv[RANK], kv[RANK];
    float nq = 0.f, nk = 0.f;
#pragma unroll
    for (int r = 0; r < RANK; r++) {
        qv[r] = rq[i * RANK + r]; kv[r] = rk[j * RANK + r];
        nq += qv[r] * qv[r];      nk += kv[r] * kv[r];
    }
    float iq = 1.f / fmaxf(sqrtf(nq), 1e-12f);
    float ik = 1.f / fmaxf(sqrtf(nk), 1e-12f);
    float dot = 0.f;
#pragma unroll
    for (int r = 0; r < RANK; r++) dot += (qv[r] * iq) * (kv[r] * ik);
    A[idx] = dot * 2.0794415416798357f;
}

// ---------------- rope table --------------------------------------------------
__global__ void rope_kernel(float2* __restrict__ tab) {
    int idx = blockIdx.x * blockDim.x + threadIdx.x;
    if (idx >= S_LEN * 32) return;
    int spos = idx >> 5, i = idx & 31;
    float div = expf((float)(2 * i) * (-0.14391156831212786f)); // -ln(1e4)/64
    float ang = (float)spos * div;
    float sn, cs;
    sincosf(ang, &sn, &cs);
    tab[idx] = make_float2(cs, sn);
}

// --------- per-(b,q): top-32 threshold + allowed-rule 64-bit mask ------------
__global__ void thr_allow_kernel(const int* __restrict__ rules, const float* __restrict__ A,
                                 unsigned long long* __restrict__ allow) {
    int bq = blockIdx.x;
    int b = bq >> 10, q = bq & 1023;
    __shared__ int   cnt[NRULES];
    __shared__ float row[NRULES];
    __shared__ float thr_s;
    __shared__ unsigned bits[2];
    int t = threadIdx.x;      // 64 threads
    cnt[t] = 0;
    if (t == 0) thr_s = NEGINF;
    __syncthreads();
    const int* rb = rules + b * S_LEN;
    for (int k = t; k <= q; k += 64) atomicAdd(&cnt[rb[k]], 1);
    row[t] = A[rb[q] * NRULES + t];
    __syncthreads();
    if (q >= TOPK - 1) {
        float v = row[t];
        int   c = cnt[t];
        int greater = 0;
#pragma unroll 8
        for (int r = 0; r < NRULES; r++) greater += (row[r] > v) ? cnt[r] : 0;
        if (c > 0 && greater < TOPK && greater + c >= TOPK)
            thr_s = v;
    }
    __syncthreads();
    unsigned bal = __ballot_sync(0xffffffffu, row[t] >= thr_s);
    if ((t & 31) == 0) bits[t >> 5] = bal;
    __syncthreads();
    if (t == 0)
        allow[bq] = (unsigned long long)bits[0] | ((unsigned long long)bits[1] << 32);
}

// -------- GEMM1 (tf32 MMA, split-K, merged z): partials ----------------------
// C[4096, NZ*32] = X[4096,1024] @ W_z[1024,32]; M-tile 128, split-K = 4.
#define X_STR 36
#define B_STR 104
#define G1_SMEM ((2 * 128 * X_STR + 2 * 32 * B_STR) * 4)

template <int NZ>
__global__ void __launch_bounds__(128)
gemm1_tc(const float* __restrict__ X, const float* __restrict__ W0,
         const float* __restrict__ W1, const float* __restrict__ W2,
         float* __restrict__ P) {
    extern __shared__ float sm[];
    float* Xs = sm;                        // [2][128][36]
    float* Bs = sm + 2 * 128 * X_STR;      // [2][32][104]
    const float* Ws[3] = {W0, W1, W2};

    const int tid = threadIdx.x;
    const int warp = tid >> 5, lane = tid & 31;
    const int g = lane >> 2, tq = lane & 3;
    const int rbase = warp * 32;
    const int rowBase = blockIdx.x * 128;
    const int kBase = blockIdx.y * (D_MODEL / KSPLIT);

    float acc[2][NZ * 4][4];
#pragma unroll
    for (int a = 0; a < 2; a++)
#pragma unroll
        for (int nt = 0; nt < NZ * 4; nt++)
#pragma unroll
            for (int j = 0; j < 4; j++) acc[a][nt][j] = 0.f;

    // staging lambda-equivalent
    auto stage = [&](int buf, int k0) {
        float* Xb = Xs + buf * 128 * X_STR;
#pragma unroll
        for (int i = 0; i < 8; i++) {      // X: 1024 float4
            int f = tid + i * 128;
            int r = f >> 3, c4 = (f & 7) * 4;
            cp16(Xb + r * X_STR + c4, X + (size_t)(rowBase + r) * D_MODEL + k0 + c4);
        }
        float* Bb = Bs + buf * 32 * B_STR;
#pragma unroll
        for (int i = 0; i < NZ * 2; i++) { // B: NZ*256 float4
            int f = tid + i * 128;
            int k = f / (NZ * 8);
            int rem = f - k * (NZ * 8);
            int z = rem >> 3, c4 = (rem & 7) * 4;
            cp16(Bb + k * B_STR + z * 32 + c4, Ws[z] + (size_t)(k0 + k) * SRANK + c4);
        }
    };

    stage(0, kBase);
    cp_commit();

    const int nchunk = (D_MODEL / KSPLIT) / 32;   // 8
    for (int c = 0; c < nchunk; c++) {
        int buf = c & 1;
        if (c + 1 < nchunk) {
            stage(buf ^ 1, kBase + (c + 1) * 32);
            cp_commit();
            cp_wait<1>();
        } else {
            cp_wait<0>();
        }
        __syncthreads();
        const float* Xb = Xs + buf * 128 * X_STR;
        const float* Bb = Bs + buf * 32 * B_STR;
#pragma unroll
        for (int kk = 0; kk < 4; kk++) {
            unsigned a0[4], a1[4];
            a0[0] = f2tf(Xb[(rbase + g)      * X_STR + kk * 8 + tq]);
            a0[1] = f2tf(Xb[(rbase + g + 8)  * X_STR + kk * 8 + tq]);
            a0[2] = f2tf(Xb[(rbase + g)      * X_STR + kk * 8 + tq + 4]);
            a0[3] = f2tf(Xb[(rbase + g + 8)  * X_STR + kk * 8 + tq + 4]);
            a1[0] = f2tf(Xb[(rbase + g + 16) * X_STR + kk * 8 + tq]);
            a1[1] = f2tf(Xb[(rbase + g + 24) * X_STR + kk * 8 + tq]);
            a1[2] = f2tf(Xb[(rbase + g + 16) * X_STR + kk * 8 + tq + 4]);
            a1[3] = f2tf(Xb[(rbase + g + 24) * X_STR + kk * 8 + tq + 4]);
#pragma unroll
            for (int nt = 0; nt < NZ * 4; nt++) {
                unsigned b0 = f2tf(Bb[(kk * 8 + tq)     * B_STR + nt * 8 + g]);
                unsigned b1 = f2tf(Bb[(kk * 8 + tq + 4) * B_STR + nt * 8 + g]);
                mma_tf32(acc[0][nt], a0, b0, b1);
                mma_tf32(acc[1][nt], a1, b0, b1);
            }
        }
        __syncthreads();
    }

#pragma unroll
    for (int a = 0; a < 2; a++)
#pragma unroll
        for (int nt = 0; nt < NZ * 4; nt++) {
            int z = nt >> 2;
            int col = (nt & 3) * 8 + 2 * tq;
            int row0 = rowBase + rbase + a * 16 + g;
            float* dst = P + ((size_t)(blockIdx.y * 3 + z) * NTOK) * SRANK;
            *(float2*)(dst + (size_t)row0 * SRANK + col) =
                make_float2(acc[a][nt][0], acc[a][nt][1]);
            *(float2*)(dst + (size_t)(row0 + 8) * SRANK + col) =
                make_float2(acc[a][nt][2], acc[a][nt][3]);
        }
}

__global__ void reduce_kernel(const float* __restrict__ P, float* __restrict__ T, int nz) {
    int idx = blockIdx.x * blockDim.x + threadIdx.x;
    if (idx >= nz * NTOK * SRANK) return;
    int z = idx / (NTOK * SRANK);
    int off = idx - z * (NTOK * SRANK);
    float s = 0.f;
#pragma unroll
    for (int ks = 0; ks < KSPLIT; ks++)
        s += P[(size_t)(ks * 3 + z) * NTOK * SRANK + off];
    T[(size_t)z * NTOK * SRANK + off] = s;
}

// ---------------- GEMM2: C_z[4096,1024] = T[z][4096,32] * W_z[32,1024] -------
__global__ void __launch_bounds__(256)
gemm2_kernel(const float* __restrict__ T, const float* __restrict__ W0,
             const float* __restrict__ W1, const float* __restrict__ W2,
             float* __restrict__ C0, float* __restrict__ C1, float* __restrict__ C2) {
    __shared__ float As[64][36];
    __shared__ float Bt[64][36];
    int tid = threadIdx.x;
    int tx = tid & 15, ty = tid >> 4;
    int z = blockIdx.z;
    const float* W = (z == 0) ? W0 : (z == 1) ? W1 : W2;
    float* C = (z == 0) ? C0 : (z == 1) ? C1 : C2;
    const float* A = T + (size_t)z * NTOK * SRANK;
    int rowBase = blockIdx.x * 64, colBase = blockIdx.y * 64;

#pragma unroll
    for (int i = 0; i < 2; i++) {
        int f = tid + i * 256;
        int r = f >> 3, kq = f & 7;
        float4 v = *(const float4*)(A + (size_t)(rowBase + r) * SRANK + kq * 4);
        *(float4*)&As[r][kq * 4] = v;
    }
#pragma unroll
    for (int i = 0; i < 8; i++) {
        int f = tid + i * 256;
        int k = f >> 6, c = f & 63;
        Bt[c][k] = W[(size_t)k * D_MODEL + colBase + c];
    }
    __syncthreads();

    float acc[4][4];
#pragma unroll
    for (int i = 0; i < 4; i++)
#pragma unroll
        for (int j = 0; j < 4; j++) acc[i][j] = 0.f;
#pragma unroll
    for (int kq = 0; kq < 8; kq++) {
        float4 a[4], bb[4];
#pragma unroll
        for (int i = 0; i < 4; i++) a[i]  = *(float4*)&As[ty + 16 * i][kq * 4];
#pragma unroll
        for (int j = 0; j < 4; j++) bb[j] = *(float4*)&Bt[tx + 16 * j][kq * 4];
#pragma unroll
        for (int i = 0; i < 4; i++)
#pragma unroll
            for (int j = 0; j < 4; j++)
                acc[i][j] += a[i].x * bb[j].x + a[i].y * bb[j].y
                           + a[i].z * bb[j].z + a[i].w * bb[j].w;
    }
#pragma unroll
    for (int i = 0; i < 4; i++)
#pragma unroll
        for (int j = 0; j < 4; j++)
            C[(size_t)(rowBase + ty + 16 * i) * D_MODEL + colBase + tx + 16 * j] = acc[i][j];
}

// -------- adapters (up to 3 projections per block, sharing the x load) -------
struct AdpArgs {
    const float* ri[3];
    const float* ro[3];
    const float* lg[3];
    float*       base[3];
    int nproj;
    int ropemask;
    int tfmask;
};

__global__ void __launch_bounds__(128)
adapter_kernel(const float* __restrict__ X, const int* __restrict__ rules,
               const float2* __restrict__ rope, AdpArgs A) {
    __shared__ float xs[D_MODEL];
    __shared__ float ris[HD * RANK];
    __shared__ float ros[RANK * HD];
    __shared__ float hs[NBLK * RANK];
    __shared__ float sels[NBLK];
    int n = blockIdx.x;
    int t = threadIdx.x;
    int rule = rules[n];

    const float4* x4 = (const float4*)(X + (size_t)n * D_MODEL);
    float4* xs4 = (float4*)xs;
    xs4[t] = x4[t];
    xs4[t + 128] = x4[t + 128];

    int spos = n & (S_LEN - 1);
    int d0 = t * 8;
    int dh0 = d0 & 63;
    int blk = t >> 3;

    for (int p = 0; p < A.nproj; p++) {
#pragma unroll
        for (int i = 0; i < 4; i++) {
            ris[t + i * 128] = A.ri[p][rule * 512 + t + i * 128];
            ros[t + i * 128] = A.ro[p][rule * 512 + t + i * 128];
        }
        if (t < 32) {
            int j = t & 15;
            float v = A.lg[p][rule * NBLK + j] * 4.0f;
            float mx = v;
#pragma unroll
            for (int msk = 8; msk >= 1; msk >>= 1)
                mx = fmaxf(mx, __shfl_xor_sync(0xffffffffu, mx, msk));
            float e = expf(v - mx);
            float sm2 = e;
#pragma unroll
            for (int msk = 8; msk >= 1; msk >>= 1)
                sm2 += __shfl_xor_sync(0xffffffffu, sm2, msk);
            if (t < 16) sels[t] = e / sm2;
        }
        __syncthreads();
        {
            int bb = t >> 3, r = t & 7;
            float sum = 0.f;
#pragma unroll
            for (int sx = 0; sx < 64; sx++) sum += xs[bb * 64 + sx] * ris[sx * 8 + r];
            hs[t] = sum;
        }
        __syncthreads();
        float hl[8];
#pragma unroll
        for (int r = 0; r < 8; r++) hl[r] = hs[blk * 8 + r];
        float selv = sels[blk];
        float* Base = A.base[p];
        float4 b0 = *(float4*)(Base + (size_t)n * D_MODEL + d0);
        float4 b1 = *(float4*)(Base + (size_t)n * D_MODEL + d0 + 4);
        float outv[8] = {b0.x, b0.y, b0.z, b0.w, b1.x, b1.y, b1.z, b1.w};
        float av[8] = {0.f, 0.f, 0.f, 0.f, 0.f, 0.f, 0.f, 0.f};
#pragma unroll
        for (int r = 0; r < 8; r++) {
            float4 r0 = *(float4*)&ros[r * 64 + dh0];
            float4 r1 = *(float4*)&ros[r * 64 + dh0 + 4];
            av[0] += hl[r] * r0.x; av[1] += hl[r] * r0.y;
            av[2] += hl[r] * r0.z; av[3] += hl[r] * r0.w;
            av[4] += hl[r] * r1.x; av[5] += hl[r] * r1.y;
            av[6] += hl[r] * r1.z; av[7] += hl[r] * r1.w;
        }
#pragma unroll
        for (int c = 0; c < 8; c++) outv[c] += av[c] * selv;
        if ((A.ropemask >> p) & 1) {
#pragma unroll
            for (int pp = 0; pp < 4; pp++) {
                int i = (dh0 + 2 * pp) >> 1;
                float2 cs = __ldg(&rope[spos * 32 + i]);
                float t1 = outv[2 * pp], t2 = outv[2 * pp + 1];
                outv[2 * pp]     = t1 * cs.x - t2 * cs.y;
                outv[2 * pp + 1] = t2 * cs.x + t1 * cs.y;
            }
        }
        if ((A.tfmask >> p) & 1) {
#pragma unroll
            for (int c = 0; c < 8; c++) outv[c] = __uint_as_float(f2tf(outv[c]));
        }
        *(float4*)(Base + (size_t)n * D_MODEL + d0)     = make_float4(outv[0], outv[1], outv[2], outv[3]);
        *(float4*)(Base + (size_t)n * D_MODEL + d0 + 4) = make_float4(outv[4], outv[5], outv[6], outv[7]);
        __syncthreads();
    }
}

// ------------------------- flash attention (tf32 MMA) ------------------------
// q-tile = 128 rows/CTA; 4 warps, each owns 32 rows = 2 A-fragment groups that
// SHARE every K/V B-fragment load (halves smem traffic per MMA).
#define QS_STR 68
#define VS_STR 72
#define FLASH_SMEM ((2 * 64 * QS_STR + 2 * 64 * VS_STR + 128) * 4)

__global__ void __launch_bounds__(128)
flash_tc(const float* __restrict__ Q, const float* __restrict__ K,
         const float* __restrict__ V, const int* __restrict__ rules,
         const unsigned long long* __restrict__ allow, float* __restrict__ O) {
    extern __shared__ float sm[];
    float* ksb[2]; float* vsb[2]; int* rkb[2];
    ksb[0] = sm;
    ksb[1] = ksb[0] + 64 * QS_STR;
    vsb[0] = ksb[1] + 64 * QS_STR;
    vsb[1] = vsb[0] + 64 * VS_STR;
    rkb[0] = (int*)(vsb[1] + 64 * VS_STR);
    rkb[1] = rkb[0] + 64;

    const int tid  = threadIdx.x;
    const int warp = tid >> 5, lane = tid & 31;
    const int g = lane >> 2, tq = lane & 3;
    const int qt = gridDim.x - 1 - blockIdx.x;     // heavy blocks first
    const int b = blockIdx.y >> 4, h = blockIdx.y & 15;
    const int tokBase = b * S_LEN;
    const int qbase = qt * 128;
    const int rbase = warp * 32;
    const int nkt = 2 * qt + 2;

    const int ldr = tid >> 4, ldc = (tid & 15) * 4;

    // ---- issue async copy of k-tile 0 ----
    {
        float* ks = ksb[0]; float* vs = vsb[0];
#pragma unroll
        for (int i = 0; i < 8; i++) {
            int r = ldr + i * 8;
            size_t go = (size_t)(tokBase + r) * D_MODEL + h * 64 + ldc;
            cp16(ks + r * QS_STR + ldc, K + go);
            cp16(vs + r * VS_STR + ldc, V + go);
        }
        cp_commit();
        if (tid < 64) rkb[0][tid] = rules[tokBase + tid];
    }

    const int rowA0 = qbase + rbase + g;       // group0 rows: rowA0, rowA0+8
    const int rowB0 = rowA0 + 16;              // group1 rows: rowB0, rowB0+8

    // ---- Q fragments direct from gmem (already tf32) ----
    unsigned qa0[8][4], qa1[8][4];
    {
        const float* Qa0 = Q + (size_t)(tokBase + rowA0) * D_MODEL + h * 64;
        const float* Qa1 = Qa0 + 8 * D_MODEL;
        const float* Qb0 = Qa0 + 16 * D_MODEL;
        const float* Qb1 = Qa0 + 24 * D_MODEL;
#pragma unroll
        for (int kk = 0; kk < 8; kk++) {
            qa0[kk][0] = __float_as_uint(Qa0[kk * 8 + tq]);
            qa0[kk][1] = __float_as_uint(Qa1[kk * 8 + tq]);
            qa0[kk][2] = __float_as_uint(Qa0[kk * 8 + tq + 4]);
            qa0[kk][3] = __float_as_uint(Qa1[kk * 8 + tq + 4]);
            qa1[kk][0] = __float_as_uint(Qb0[kk * 8 + tq]);
            qa1[kk][1] = __float_as_uint(Qb1[kk * 8 + tq]);
            qa1[kk][2] = __float_as_uint(Qb0[kk * 8 + tq + 4]);
            qa1[kk][3] = __float_as_uint(Qb1[kk * 8 + tq + 4]);
        }
    }

    const unsigned long long al0 = allow[b * S_LEN + rowA0];
    const unsigned long long al1 = allow[b * S_LEN + rowA0 + 8];
    const unsigned long long al2 = allow[b * S_LEN + rowB0];
    const unsigned long long al3 = allow[b * S_LEN + rowB0 + 8];

    float o0[8][4], o1[8][4];
#pragma unroll
    for (int nt = 0; nt < 8; nt++)
#pragma unroll
        for (int j = 0; j < 4; j++) { o0[nt][j] = 0.f; o1[nt][j] = 0.f; }
    float m0 = NEGINF, m1 = NEGINF, m2 = NEGINF, m3 = NEGINF;
    float l0 = 0.f, l1 = 0.f, l2 = 0.f, l3 = 0.f;

    for (int kt = 0; kt < nkt; kt++) {
        const int buf = kt & 1;
        __syncthreads();
        if (kt + 1 < nkt) {
            float* ks = ksb[buf ^ 1]; float* vs = vsb[buf ^ 1];
#pragma unroll
            for (int i = 0; i < 8; i++) {
                int r = ldr + i * 8;
                size_t go = (size_t)(tokBase + (kt + 1) * 64 + r) * D_MODEL + h * 64 + ldc;
                cp16(ks + r * QS_STR + ldc, K + go);
                cp16(vs + r * VS_STR + ldc, V + go);
            }
            cp_commit();
            if (tid < 64) rkb[buf ^ 1][tid] = rules[tokBase + (kt + 1) * 64 + tid];
            cp_wait<1>();
        } else {
            cp_wait<0>();
        }
        __syncthreads();

        const float* ks = ksb[buf];
        const float* vs = vsb[buf];
        const int*   rk_s = rkb[buf];

        // ---- S = Q K^T (B frags shared across groups) ----
        float s0[8][4], s1[8][4];
#pragma unroll
        for (int nt = 0; nt < 8; nt++)
#pragma unroll
            for (int j = 0; j < 4; j++) { s0[nt][j] = 0.f; s1[nt][j] = 0.f; }
#pragma unroll
        for (int kk = 0; kk < 8; kk++) {
#pragma unroll
            for (int nt = 0; nt < 8; nt++) {
                unsigned b0 = __float_as_uint(ks[(nt * 8 + g) * QS_STR + kk * 8 + tq]);
                unsigned b1 = __float_as_uint(ks[(nt * 8 + g) * QS_STR + kk * 8 + tq + 4]);
                mma_tf32(s0[nt], qa0[kk], b0, b1);
                mma_tf32(s1[nt], qa1[kk], b0, b1);
            }
        }

        // ---- mask + scale ----
        const bool noDiag = (kt < 2 * qt);
#pragma unroll
        for (int nt = 0; nt < 8; nt++) {
            int c0 = nt * 8 + 2 * tq;
            int rk0 = rk_s[c0], rk1 = rk_s[c0 + 1];
            int col0 = kt * 64 + c0;
            bool k0a = (al0 >> rk0) & 1ULL, k1a = (al0 >> rk1) & 1ULL;
            bool k0b = (al1 >> rk0) & 1ULL, k1b = (al1 >> rk1) & 1ULL;
            bool k0c = (al2 >> rk0) & 1ULL, k1c = (al2 >> rk1) & 1ULL;
            bool k0d = (al3 >> rk0) & 1ULL, k1d = (al3 >> rk1) & 1ULL;
            s0[nt][0] = (k0a && (noDiag || col0     <= rowA0    )) ? s0[nt][0] * 0.125f : NEGINF;
            s0[nt][1] = (k1a && (noDiag || col0 + 1 <= rowA0    )) ? s0[nt][1] * 0.125f : NEGINF;
            s0[nt][2] = (k0b && (noDiag || col0     <= rowA0 + 8)) ? s0[nt][2] * 0.125f : NEGINF;
            s0[nt][3] = (k1b && (noDiag || col0 + 1 <= rowA0 + 8)) ? s0[nt][3] * 0.125f : NEGINF;
            s1[nt][0] = (k0c && (noDiag || col0     <= rowB0    )) ? s1[nt][0] * 0.125f : NEGINF;
            s1[nt][1] = (k1c && (noDiag || col0 + 1 <= rowB0    )) ? s1[nt][1] * 0.125f : NEGINF;
            s1[nt][2] = (k0d && (noDiag || col0     <= rowB0 + 8)) ? s1[nt][2] * 0.125f : NEGINF;
            s1[nt][3] = (k1d && (noDiag || col0 + 1 <= rowB0 + 8)) ? s1[nt][3] * 0.125f : NEGINF;
        }

        // ---- online softmax (4 row-halves) ----
        float mx0 = NEGINF, mx1 = NEGINF, mx2 = NEGINF, mx3 = NEGINF;
#pragma unroll
        for (int nt = 0; nt < 8; nt++) {
            mx0 = fmaxf(mx0, fmaxf(s0[nt][0], s0[nt][1]));
            mx1 = fmaxf(mx1, fmaxf(s0[nt][2], s0[nt][3]));
            mx2 = fmaxf(mx2, fmaxf(s1[nt][0], s1[nt][1]));
            mx3 = fmaxf(mx3, fmaxf(s1[nt][2], s1[nt][3]));
        }
#pragma unroll
        for (int msk = 1; msk <= 2; msk <<= 1) {
            mx0 = fmaxf(mx0, __shfl_xor_sync(0xffffffffu, mx0, msk));
            mx1 = fmaxf(mx1, __shfl_xor_sync(0xffffffffu, mx1, msk));
            mx2 = fmaxf(mx2, __shfl_xor_sync(0xffffffffu, mx2, msk));
            mx3 = fmaxf(mx3, __shfl_xor_sync(0xffffffffu, mx3, msk));
        }
        float mn0 = fmaxf(m0, mx0), mn1 = fmaxf(m1, mx1);
        float mn2 = fmaxf(m2, mx2), mn3 = fmaxf(m3, mx3);
        float cr0 = (m0 == mn0) ? 1.f : __expf(m0 - mn0);
        float cr1 = (m1 == mn1) ? 1.f : __expf(m1 - mn1);
        float cr2 = (m2 == mn2) ? 1.f : __expf(m2 - mn2);
        float cr3 = (m3 == mn3) ? 1.f : __expf(m3 - mn3);
        float rs0 = 0.f, rs1 = 0.f, rs2 = 0.f, rs3 = 0.f;
#pragma unroll
        for (int nt = 0; nt < 8; nt++) {
            s0[nt][0] = (mn0 == NEGINF) ? 0.f : __expf(s0[nt][0] - mn0);
            s0[nt][1] = (mn0 == NEGINF) ? 0.f : __expf(s0[nt][1] - mn0);
            s0[nt][2] = (mn1 == NEGINF) ? 0.f : __expf(s0[nt][2] - mn1);
            s0[nt][3] = (mn1 == NEGINF) ? 0.f : __expf(s0[nt][3] - mn1);
            s1[nt][0] = (mn2 == NEGINF) ? 0.f : __expf(s1[nt][0] - mn2);
            s1[nt][1] = (mn2 == NEGINF) ? 0.f : __expf(s1[nt][1] - mn2);
            s1[nt][2] = (mn3 == NEGINF) ? 0.f : __expf(s1[nt][2] - mn3);
            s1[nt][3] = (mn3 == NEGINF) ? 0.f : __expf(s1[nt][3] - mn3);
            rs0 += s0[nt][0] + s0[nt][1];
            rs1 += s0[nt][2] + s0[nt][3];
            rs2 += s1[nt][0] + s1[nt][1];
            rs3 += s1[nt][2] + s1[nt][3];
        }
#pragma unroll
        for (int msk = 1; msk <= 2; msk <<= 1) {
            rs0 += __shfl_xor_sync(0xffffffffu, rs0, msk);
            rs1 += __shfl_xor_sync(0xffffffffu, rs1, msk);
            rs2 += __shfl_xor_sync(0xffffffffu, rs2, msk);
            rs3 += __shfl_xor_sync(0xffffffffu, rs3, msk);
        }
        l0 = l0 * cr0 + rs0; l1 = l1 * cr1 + rs1;
        l2 = l2 * cr2 + rs2; l3 = l3 * cr3 + rs3;
        m0 = mn0; m1 = mn1; m2 = mn2; m3 = mn3;
#pragma unroll
        for (int nt = 0; nt < 8; nt++) {
            o0[nt][0] *= cr0; o0[nt][1] *= cr0; o0[nt][2] *= cr1; o0[nt][3] *= cr1;
            o1[nt][0] *= cr2; o1[nt][1] *= cr2; o1[nt][2] *= cr3; o1[nt][3] *= cr3;
        }

        // ---- round P to tf32 ----
#pragma unroll
        for (int nt = 0; nt < 8; nt++)
#pragma unroll
            for (int j = 0; j < 4; j++) {
                s0[nt][j] = __uint_as_float(f2tf(s0[nt][j]));
                s1[nt][j] = __uint_as_float(f2tf(s1[nt][j]));
            }

        // ---- O += P V (B frags shared; P via quad shuffles) ----
        const unsigned srcA = (lane & 28) | (tq >> 1);
        const unsigned srcB = srcA + 2;
        const bool odd = (tq & 1);
#pragma unroll
        for (int kk = 0; kk < 8; kk++) {
            unsigned pa0[4], pa1[4];
            {
                float x0 = __shfl_sync(0xffffffffu, s0[kk][0], srcA);
                float x1 = __shfl_sync(0xffffffffu, s0[kk][1], srcA);
                float x2 = __shfl_sync(0xffffffffu, s0[kk][2], srcA);
                float x3 = __shfl_sync(0xffffffffu, s0[kk][3], srcA);
                float y0 = __shfl_sync(0xffffffffu, s0[kk][0], srcB);
                float y1 = __shfl_sync(0xffffffffu, s0[kk][1], srcB);
                float y2 = __shfl_sync(0xffffffffu, s0[kk][2], srcB);
                float y3 = __shfl_sync(0xffffffffu, s0[kk][3], srcB);
                pa0[0] = __float_as_uint(odd ? x1 : x0);
                pa0[1] = __float_as_uint(odd ? x3 : x2);
                pa0[2] = __float_as_uint(odd ? y1 : y0);
                pa0[3] = __float_as_uint(odd ? y3 : y2);
            }
            {
                float x0 = __shfl_sync(0xffffffffu, s1[kk][0], srcA);
                float x1 = __shfl_sync(0xffffffffu, s1[kk][1], srcA);
                float x2 = __shfl_sync(0xffffffffu, s1[kk][2], srcA);
                float x3 = __shfl_sync(0xffffffffu, s1[kk][3], srcA);
                float y0 = __shfl_sync(0xffffffffu, s1[kk][0], srcB);
                float y1 = __shfl_sync(0xffffffffu, s1[kk][1], srcB);
                float y2 = __shfl_sync(0xffffffffu, s1[kk][2], srcB);
                float y3 = __shfl_sync(0xffffffffu, s1[kk][3], srcB);
                pa1[0] = __float_as_uint(odd ? x1 : x0);
                pa1[1] = __float_as_uint(odd ? x3 : x2);
                pa1[2] = __float_as_uint(odd ? y1 : y0);
                pa1[3] = __float_as_uint(odd ? y3 : y2);
            }
#pragma unroll
            for (int nt = 0; nt < 8; nt++) {
                unsigned b0 = __float_as_uint(vs[(kk * 8 + tq) * VS_STR + nt * 8 + g]);
                unsigned b1 = __float_as_uint(vs[(kk * 8 + tq + 4) * VS_STR + nt * 8 + g]);
                mma_tf32(o0[nt], pa0, b0, b1);
                mma_tf32(o1[nt], pa1, b0, b1);
            }
        }
    }

    float i0 = 1.f / l0, i1 = 1.f / l1, i2 = 1.f / l2, i3 = 1.f / l3;
#pragma unroll
    for (int nt = 0; nt < 8; nt++) {
        *(float2*)(O + (size_t)(tokBase + rowA0)      * D_MODEL + h * 64 + nt * 8 + 2 * tq) =
            make_float2(o0[nt][0] * i0, o0[nt][1] * i0);
        *(float2*)(O + (size_t)(tokBase + rowA0 + 8)  * D_MODEL + h * 64 + nt * 8 + 2 * tq) =
            make_float2(o0[nt][2] * i1, o0[nt][3] * i1);
        *(float2*)(O + (size_t)(tokBase + rowB0)      * D_MODEL + h * 64 + nt * 8 + 2 * tq) =
            make_float2(o1[nt][0] * i2, o1[nt][1] * i2);
        *(float2*)(O + (size_t)(tokBase + rowB0 + 8)  * D_MODEL + h * 64 + nt * 8 + 2 * tq) =
            make_float2(o1[nt][2] * i3, o1[nt][3] * i3);
    }
}

// ----------------------------------------------------------------------------
extern "C" void kernel_launch(void* const* d_in, const int* in_sizes, int n_in,
                              void* d_out, int out_size) {
    const float* x     = (const float*)d_in[0];
    const int*   rules = (const int*)  d_in[1];
    const float* q_si = (const float*)d_in[2],  *q_so = (const float*)d_in[3];
    const float* q_ri = (const float*)d_in[4],  *q_ro = (const float*)d_in[5];
    const float* q_lg = (const float*)d_in[6];
    const float* k_si = (const float*)d_in[7],  *k_so = (const float*)d_in[8];
    const float* k_ri = (const float*)d_in[9],  *k_ro = (const float*)d_in[10];
    const float* k_lg = (const float*)d_in[11];
    const float* v_si = (const float*)d_in[12], *v_so = (const float*)d_in[13];
    const float* v_ri = (const float*)d_in[14], *v_ro = (const float*)d_in[15];
    const float* v_lg = (const float*)d_in[16];
    const float* o_si = (const float*)d_in[17], *o_so = (const float*)d_in[18];
    const float* o_ri = (const float*)d_in[19], *o_ro = (const float*)d_in[20];
    const float* o_lg = (const float*)d_in[21];
    const float* router_q = (const float*)d_in[22];
    const float* router_k = (const float*)d_in[23];
    float* out = (float*)d_out;

    float *T1, *Pp, *Qb, *Kb, *Vb, *AO, *Atab;
    float2* Rope;
    unsigned long long* Allow;
    cudaGetSymbolAddress((void**)&T1,    g_T1);
    cudaGetSymbolAddress((void**)&Pp,    g_P);
    cudaGetSymbolAddress((void**)&Qb,    g_Q);
    cudaGetSymbolAddress((void**)&Kb,    g_K);
    cudaGetSymbolAddress((void**)&Vb,    g_V);
    cudaGetSymbolAddress((void**)&AO,    g_AO);
    cudaGetSymbolAddress((void**)&Atab,  g_A);
    cudaGetSymbolAddress((void**)&Allow, g_allow);
    cudaGetSymbolAddress((void**)&Rope,  g_rope);

    aff_kernel<<<16, 256>>>(router_q, router_k, Atab);
    rope_kernel<<<64, 512>>>(Rope);
    thr_allow_kernel<<<NTOK, 64>>>(rules, Atab, Allow);

    // QKV base projections (tf32 MMA, merged z, split-K)
    cudaFuncSetAttribute(gemm1_tc<3>, cudaFuncAttributeMaxDynamicSharedMemorySize, G1_SMEM);
    cudaFuncSetAttribute(gemm1_tc<1>, cudaFuncAttributeMaxDynamicSharedMemorySize, G1_SMEM);
    gemm1_tc<3><<<dim3(32, KSPLIT), 128, G1_SMEM>>>(x, q_si, k_si, v_si, Pp);
    reduce_kernel<<<(3 * NTOK * SRANK + 255) / 256, 256>>>(Pp, T1, 3);
    gemm2_kernel<<<dim3(64, 16, 3), 256>>>(T1, q_so, k_so, v_so, Qb, Kb, Vb);

    AdpArgs aq;
    aq.ri[0] = q_ri; aq.ri[1] = k_ri; aq.ri[2] = v_ri;
    aq.ro[0] = q_ro; aq.ro[1] = k_ro; aq.ro[2] = v_ro;
    aq.lg[0] = q_lg; aq.lg[1] = k_lg; aq.lg[2] = v_lg;
    aq.base[0] = Qb; aq.base[1] = Kb; aq.base[2] = Vb;
    aq.nproj = 3; aq.ropemask = 0x3; aq.tfmask = 0x7;
    adapter_kernel<<<NTOK, 128>>>(x, rules, Rope, aq);

    // flash attention (tf32 tensor cores, 128-row q-tiles, cp.async)
    cudaFuncSetAttribute(flash_tc, cudaFuncAttributeMaxDynamicSharedMemorySize, FLASH_SMEM);
    flash_tc<<<dim3(8, 64), 128, FLASH_SMEM>>>(Qb, Kb, Vb, rules, Allow, AO);

    // O projection
    gemm1_tc<1><<<dim3(32, KSPLIT), 128, G1_SMEM>>>(AO, o_si, o_si, o_si, Pp);
    reduce_kernel<<<(NTOK * SRANK + 255) / 256, 256>>>(Pp, T1, 1);
    gemm2_kernel<<<dim3(64, 16, 1), 256>>>(T1, o_so, o_so, o_so, out, out, out);

    AdpArgs ao;
    ao.ri[0] = o_ri; ao.ri[1] = o_ri; ao.ri[2] = o_ri;
    ao.ro[0] = o_ro; ao.ro[1] = o_ro; ao.ro[2] = o_ro;
    ao.lg[0] = o_lg; ao.lg[1] = o_lg; ao.lg[2] = o_lg;
    ao.base[0] = out; ao.base[1] = out; ao.base[2] = out;
    ao.nproj = 1; ao.ropemask = 0; ao.tfmask = 0;
    adapter_kernel<<<NTOK, 128>>>(AO, rules, Rope, ao);
}

// round 10
// speedup vs baseline: 1.3725x; 1.3725x over previous
#include <cuda_runtime.h>
#include <math.h>

#define D_MODEL 1024
#define S_LEN   1024
#define BATCH   4
#define NTOK    4096
#define NHEADS  16
#define HD      64
#define NRULES  64
#define RANK    8
#define SRANK   32
#define NBLK    16
#define TOPK    32
#define KSPLIT  4

#define NEGINF (__int_as_float(0xff800000))

// ---------------- scratch (device globals; no allocation allowed) ------------
__device__ float g_T1[3 * NTOK * SRANK];
__device__ float g_P [KSPLIT * 3 * NTOK * SRANK];
__device__ float g_Q [NTOK * D_MODEL];
__device__ float g_K [NTOK * D_MODEL];
__device__ float g_V [NTOK * D_MODEL];
__device__ float g_AO[NTOK * D_MODEL];
__device__ float g_A [NRULES * NRULES];
__device__ unsigned long long g_allow[NTOK];
__device__ float2 g_rope[S_LEN * 32];

__device__ __forceinline__ unsigned f2tf(float x) {
    unsigned u;
    asm("cvt.rna.tf32.f32 %0, %1;" : "=r"(u) : "f"(x));
    return u;
}

__device__ __forceinline__ void mma_tf32(float d[4], const unsigned a[4],
                                         unsigned b0, unsigned b1) {
    asm volatile(
        "mma.sync.aligned.m16n8k8.row.col.f32.tf32.tf32.f32 "
        "{%0,%1,%2,%3}, {%4,%5,%6,%7}, {%8,%9}, {%0,%1,%2,%3};\n"
        : "+f"(d[0]), "+f"(d[1]), "+f"(d[2]), "+f"(d[3])
        : "r"(a[0]), "r"(a[1]), "r"(a[2]), "r"(a[3]), "r"(b0), "r"(b1));
}

__device__ __forceinline__ void cp16(float* smem_dst, const float* gsrc) {
    unsigned s = (unsigned)__cvta_generic_to_shared(smem_dst);
    asm volatile("cp.async.cg.shared.global [%0], [%1], 16;" :: "r"(s), "l"(gsrc));
}
__device__ __forceinline__ void cp_commit() {
    asm volatile("cp.async.commit_group;");
}
template <int N>
__device__ __forceinline__ void cp_wait() {
    asm volatile("cp.async.wait_group %0;" :: "n"(N));
}

// ---------------- affinity table ---------------------------------------------
__global__ void aff_kernel(const float* __restrict__ rq, const float* __restrict__ rk,
                           float* __restrict__ A) {
    int idx = blockIdx.x * blockDim.x + threadIdx.x;
    if (idx >= NRULES * NRULES) return;
    int i = idx >> 6, j = idx & 63;
    float qv[RANK], kv[RANK];
    float nq = 0.f, nk = 0.f;
#pragma unroll
    for (int r = 0; r < RANK; r++) {
        qv[r] = rq[i * RANK + r]; kv[r] = rk[j * RANK + r];
        nq += qv[r] * qv[r];      nk += kv[r] * kv[r];
    }
    float iq = 1.f / fmaxf(sqrtf(nq), 1e-12f);
    float ik = 1.f / fmaxf(sqrtf(nk), 1e-12f);
    float dot = 0.f;
#pragma unroll
    for (int r = 0; r < RANK; r++) dot += (qv[r] * iq) * (kv[r] * ik);
    A[idx] = dot * 2.0794415416798357f;
}

// ---------------- rope table --------------------------------------------------
__global__ void rope_kernel(float2* __restrict__ tab) {
    int idx = blockIdx.x * blockDim.x + threadIdx.x;
    if (idx >= S_LEN * 32) return;
    int spos = idx >> 5, i = idx & 31;
    float div = expf((float)(2 * i) * (-0.14391156831212786f)); // -ln(1e4)/64
    float ang = (float)spos * div;
    float sn, cs;
    sincosf(ang, &sn, &cs);
    tab[idx] = make_float2(cs, sn);
}

// --------- per-(b,q): top-32 threshold + allowed-rule 64-bit mask ------------
__global__ void thr_allow_kernel(const int* __restrict__ rules, const float* __restrict__ A,
                                 unsigned long long* __restrict__ allow) {
    int bq = blockIdx.x;
    int b = bq >> 10, q = bq & 1023;
    __shared__ int   cnt[NRULES];
    __shared__ float row[NRULES];
    __shared__ float thr_s;
    __shared__ unsigned bits[2];
    int t = threadIdx.x;      // 64 threads
    cnt[t] = 0;
    if (t == 0) thr_s = NEGINF;
    __syncthreads();
    const int* rb = rules + b * S_LEN;
    for (int k = t; k <= q; k += 64) atomicAdd(&cnt[rb[k]], 1);
    row[t] = A[rb[q] * NRULES + t];
    __syncthreads();
    if (q >= TOPK - 1) {
        float v = row[t];
        int   c = cnt[t];
        int greater = 0;
#pragma unroll 8
        for (int r = 0; r < NRULES; r++) greater += (row[r] > v) ? cnt[r] : 0;
        if (c > 0 && greater < TOPK && greater + c >= TOPK)
            thr_s = v;
    }
    __syncthreads();
    unsigned bal = __ballot_sync(0xffffffffu, row[t] >= thr_s);
    if ((t & 31) == 0) bits[t >> 5] = bal;
    __syncthreads();
    if (t == 0)
        allow[bq] = (unsigned long long)bits[0] | ((unsigned long long)bits[1] << 32);
}

// -------- GEMM1 (tf32 MMA, split-K, merged z): partials ----------------------
#define X_STR 36
#define B_STR 104
#define G1_SMEM ((2 * 128 * X_STR + 2 * 32 * B_STR) * 4)

template <int NZ>
__global__ void __launch_bounds__(128)
gemm1_tc(const float* __restrict__ X, const float* __restrict__ W0,
         const float* __restrict__ W1, const float* __restrict__ W2,
         float* __restrict__ P) {
    extern __shared__ float sm[];
    float* Xs = sm;                        // [2][128][36]
    float* Bs = sm + 2 * 128 * X_STR;      // [2][32][104]
    const float* Ws[3] = {W0, W1, W2};

    const int tid = threadIdx.x;
    const int warp = tid >> 5, lane = tid & 31;
    const int g = lane >> 2, tq = lane & 3;
    const int rbase = warp * 32;
    const int rowBase = blockIdx.x * 128;
    const int kBase = blockIdx.y * (D_MODEL / KSPLIT);

    float acc[2][NZ * 4][4];
#pragma unroll
    for (int a = 0; a < 2; a++)
#pragma unroll
        for (int nt = 0; nt < NZ * 4; nt++)
#pragma unroll
            for (int j = 0; j < 4; j++) acc[a][nt][j] = 0.f;

    auto stage = [&](int buf, int k0) {
        float* Xb = Xs + buf * 128 * X_STR;
#pragma unroll
        for (int i = 0; i < 8; i++) {
            int f = tid + i * 128;
            int r = f >> 3, c4 = (f & 7) * 4;
            cp16(Xb + r * X_STR + c4, X + (size_t)(rowBase + r) * D_MODEL + k0 + c4);
        }
        float* Bb = Bs + buf * 32 * B_STR;
#pragma unroll
        for (int i = 0; i < NZ * 2; i++) {
            int f = tid + i * 128;
            int k = f / (NZ * 8);
            int rem = f - k * (NZ * 8);
            int z = rem >> 3, c4 = (rem & 7) * 4;
            cp16(Bb + k * B_STR + z * 32 + c4, Ws[z] + (size_t)(k0 + k) * SRANK + c4);
        }
    };

    stage(0, kBase);
    cp_commit();

    const int nchunk = (D_MODEL / KSPLIT) / 32;   // 8
    for (int c = 0; c < nchunk; c++) {
        int buf = c & 1;
        if (c + 1 < nchunk) {
            stage(buf ^ 1, kBase + (c + 1) * 32);
            cp_commit();
            cp_wait<1>();
        } else {
            cp_wait<0>();
        }
        __syncthreads();
        const float* Xb = Xs + buf * 128 * X_STR;
        const float* Bb = Bs + buf * 32 * B_STR;
#pragma unroll
        for (int kk = 0; kk < 4; kk++) {
            unsigned a0[4], a1[4];
            a0[0] = f2tf(Xb[(rbase + g)      * X_STR + kk * 8 + tq]);
            a0[1] = f2tf(Xb[(rbase + g + 8)  * X_STR + kk * 8 + tq]);
            a0[2] = f2tf(Xb[(rbase + g)      * X_STR + kk * 8 + tq + 4]);
            a0[3] = f2tf(Xb[(rbase + g + 8)  * X_STR + kk * 8 + tq + 4]);
            a1[0] = f2tf(Xb[(rbase + g + 16) * X_STR + kk * 8 + tq]);
            a1[1] = f2tf(Xb[(rbase + g + 24) * X_STR + kk * 8 + tq]);
            a1[2] = f2tf(Xb[(rbase + g + 16) * X_STR + kk * 8 + tq + 4]);
            a1[3] = f2tf(Xb[(rbase + g + 24) * X_STR + kk * 8 + tq + 4]);
#pragma unroll
            for (int nt = 0; nt < NZ * 4; nt++) {
                unsigned b0 = f2tf(Bb[(kk * 8 + tq)     * B_STR + nt * 8 + g]);
                unsigned b1 = f2tf(Bb[(kk * 8 + tq + 4) * B_STR + nt * 8 + g]);
                mma_tf32(acc[0][nt], a0, b0, b1);
                mma_tf32(acc[1][nt], a1, b0, b1);
            }
        }
        __syncthreads();
    }

#pragma unroll
    for (int a = 0; a < 2; a++)
#pragma unroll
        for (int nt = 0; nt < NZ * 4; nt++) {
            int z = nt >> 2;
            int col = (nt & 3) * 8 + 2 * tq;
            int row0 = rowBase + rbase + a * 16 + g;
            float* dst = P + ((size_t)(blockIdx.y * 3 + z) * NTOK) * SRANK;
            *(float2*)(dst + (size_t)row0 * SRANK + col) =
                make_float2(acc[a][nt][0], acc[a][nt][1]);
            *(float2*)(dst + (size_t)(row0 + 8) * SRANK + col) =
                make_float2(acc[a][nt][2], acc[a][nt][3]);
        }
}

__global__ void reduce_kernel(const float* __restrict__ P, float* __restrict__ T, int nz) {
    int idx = blockIdx.x * blockDim.x + threadIdx.x;
    if (idx >= nz * NTOK * SRANK) return;
    int z = idx / (NTOK * SRANK);
    int off = idx - z * (NTOK * SRANK);
    float s = 0.f;
#pragma unroll
    for (int ks = 0; ks < KSPLIT; ks++)
        s += P[(size_t)(ks * 3 + z) * NTOK * SRANK + off];
    T[(size_t)z * NTOK * SRANK + off] = s;
}

// ---------------- GEMM2: C_z[4096,1024] = T[z][4096,32] * W_z[32,1024] -------
__global__ void __launch_bounds__(256)
gemm2_kernel(const float* __restrict__ T, const float* __restrict__ W0,
             const float* __restrict__ W1, const float* __restrict__ W2,
             float* __restrict__ C0, float* __restrict__ C1, float* __restrict__ C2) {
    __shared__ float As[64][36];
    __shared__ float Bt[64][36];
    int tid = threadIdx.x;
    int tx = tid & 15, ty = tid >> 4;
    int z = blockIdx.z;
    const float* W = (z == 0) ? W0 : (z == 1) ? W1 : W2;
    float* C = (z == 0) ? C0 : (z == 1) ? C1 : C2;
    const float* A = T + (size_t)z * NTOK * SRANK;
    int rowBase = blockIdx.x * 64, colBase = blockIdx.y * 64;

#pragma unroll
    for (int i = 0; i < 2; i++) {
        int f = tid + i * 256;
        int r = f >> 3, kq = f & 7;
        float4 v = *(const float4*)(A + (size_t)(rowBase + r) * SRANK + kq * 4);
        *(float4*)&As[r][kq * 4] = v;
    }
#pragma unroll
    for (int i = 0; i < 8; i++) {
        int f = tid + i * 256;
        int k = f >> 6, c = f & 63;
        Bt[c][k] = W[(size_t)k * D_MODEL + colBase + c];
    }
    __syncthreads();

    float acc[4][4];
#pragma unroll
    for (int i = 0; i < 4; i++)
#pragma unroll
        for (int j = 0; j < 4; j++) acc[i][j] = 0.f;
#pragma unroll
    for (int kq = 0; kq < 8; kq++) {
        float4 a[4], bb[4];
#pragma unroll
        for (int i = 0; i < 4; i++) a[i]  = *(float4*)&As[ty + 16 * i][kq * 4];
#pragma unroll
        for (int j = 0; j < 4; j++) bb[j] = *(float4*)&Bt[tx + 16 * j][kq * 4];
#pragma unroll
        for (int i = 0; i < 4; i++)
#pragma unroll
            for (int j = 0; j < 4; j++)
                acc[i][j] += a[i].x * bb[j].x + a[i].y * bb[j].y
                           + a[i].z * bb[j].z + a[i].w * bb[j].w;
    }
#pragma unroll
    for (int i = 0; i < 4; i++)
#pragma unroll
        for (int j = 0; j < 4; j++)
            C[(size_t)(rowBase + ty + 16 * i) * D_MODEL + colBase + tx + 16 * j] = acc[i][j];
}

// -------- adapters (up to 3 projections per block, sharing the x load) -------
struct AdpArgs {
    const float* ri[3];
    const float* ro[3];
    const float* lg[3];
    float*       base[3];
    int nproj;
    int ropemask;
    int tfmask;
};

__global__ void __launch_bounds__(128)
adapter_kernel(const float* __restrict__ X, const int* __restrict__ rules,
               const float2* __restrict__ rope, AdpArgs A) {
    __shared__ float xs[D_MODEL];
    __shared__ float ris[HD * RANK];
    __shared__ float ros[RANK * HD];
    __shared__ float hs[NBLK * RANK];
    __shared__ float sels[NBLK];
    int n = blockIdx.x;
    int t = threadIdx.x;
    int rule = rules[n];

    const float4* x4 = (const float4*)(X + (size_t)n * D_MODEL);
    float4* xs4 = (float4*)xs;
    xs4[t] = x4[t];
    xs4[t + 128] = x4[t + 128];

    int spos = n & (S_LEN - 1);
    int d0 = t * 8;
    int dh0 = d0 & 63;
    int blk = t >> 3;

    for (int p = 0; p < A.nproj; p++) {
#pragma unroll
        for (int i = 0; i < 4; i++) {
            ris[t + i * 128] = A.ri[p][rule * 512 + t + i * 128];
            ros[t + i * 128] = A.ro[p][rule * 512 + t + i * 128];
        }
        if (t < 32) {
            int j = t & 15;
            float v = A.lg[p][rule * NBLK + j] * 4.0f;
            float mx = v;
#pragma unroll
            for (int msk = 8; msk >= 1; msk >>= 1)
                mx = fmaxf(mx, __shfl_xor_sync(0xffffffffu, mx, msk));
            float e = expf(v - mx);
            float sm2 = e;
#pragma unroll
            for (int msk = 8; msk >= 1; msk >>= 1)
                sm2 += __shfl_xor_sync(0xffffffffu, sm2, msk);
            if (t < 16) sels[t] = e / sm2;
        }
        __syncthreads();
        {
            int bb = t >> 3, r = t & 7;
            float sum = 0.f;
#pragma unroll
            for (int sx = 0; sx < 64; sx++) sum += xs[bb * 64 + sx] * ris[sx * 8 + r];
            hs[t] = sum;
        }
        __syncthreads();
        float hl[8];
#pragma unroll
        for (int r = 0; r < 8; r++) hl[r] = hs[blk * 8 + r];
        float selv = sels[blk];
        float* Base = A.base[p];
        float4 b0 = *(float4*)(Base + (size_t)n * D_MODEL + d0);
        float4 b1 = *(float4*)(Base + (size_t)n * D_MODEL + d0 + 4);
        float outv[8] = {b0.x, b0.y, b0.z, b0.w, b1.x, b1.y, b1.z, b1.w};
        float av[8] = {0.f, 0.f, 0.f, 0.f, 0.f, 0.f, 0.f, 0.f};
#pragma unroll
        for (int r = 0; r < 8; r++) {
            float4 r0 = *(float4*)&ros[r * 64 + dh0];
            float4 r1 = *(float4*)&ros[r * 64 + dh0 + 4];
            av[0] += hl[r] * r0.x; av[1] += hl[r] * r0.y;
            av[2] += hl[r] * r0.z; av[3] += hl[r] * r0.w;
            av[4] += hl[r] * r1.x; av[5] += hl[r] * r1.y;
            av[6] += hl[r] * r1.z; av[7] += hl[r] * r1.w;
        }
#pragma unroll
        for (int c = 0; c < 8; c++) outv[c] += av[c] * selv;
        if ((A.ropemask >> p) & 1) {
#pragma unroll
            for (int pp = 0; pp < 4; pp++) {
                int i = (dh0 + 2 * pp) >> 1;
                float2 cs = __ldg(&rope[spos * 32 + i]);
                float t1 = outv[2 * pp], t2 = outv[2 * pp + 1];
                outv[2 * pp]     = t1 * cs.x - t2 * cs.y;
                outv[2 * pp + 1] = t2 * cs.x + t1 * cs.y;
            }
        }
        if ((A.tfmask >> p) & 1) {
#pragma unroll
            for (int c = 0; c < 8; c++) outv[c] = __uint_as_float(f2tf(outv[c]));
        }
        *(float4*)(Base + (size_t)n * D_MODEL + d0)     = make_float4(outv[0], outv[1], outv[2], outv[3]);
        *(float4*)(Base + (size_t)n * D_MODEL + d0 + 4) = make_float4(outv[4], outv[5], outv[6], outv[7]);
        __syncthreads();
    }
}

// ------------------------- flash attention (tf32 MMA, R4 config) -------------
#define QS_STR 68
#define VS_STR 72
#define FLASH_SMEM ((2 * 64 * QS_STR + 2 * 64 * VS_STR + 128) * 4)

__global__ void __launch_bounds__(128)
flash_tc(const float* __restrict__ Q, const float* __restrict__ K,
         const float* __restrict__ V, const int* __restrict__ rules,
         const unsigned long long* __restrict__ allow, float* __restrict__ O) {
    extern __shared__ float sm[];
    float* ksb[2]; float* vsb[2]; int* rkb[2];
    ksb[0] = sm;
    ksb[1] = ksb[0] + 64 * QS_STR;
    vsb[0] = ksb[1] + 64 * QS_STR;
    vsb[1] = vsb[0] + 64 * VS_STR;
    rkb[0] = (int*)(vsb[1] + 64 * VS_STR);
    rkb[1] = rkb[0] + 64;

    const int tid  = threadIdx.x;
    const int warp = tid >> 5, lane = tid & 31;
    const int g = lane >> 2, tq = lane & 3;
    const int qt = gridDim.x - 1 - blockIdx.x;     // heavy blocks first
    const int b = blockIdx.y >> 4, h = blockIdx.y & 15;
    const int tokBase = b * S_LEN;
    const int rbase = warp * 16;

    const int ldr = tid >> 4, ldc = (tid & 15) * 4;

    // ---- issue async copy of tile 0 ----
    {
        float* ks = ksb[0]; float* vs = vsb[0];
#pragma unroll
        for (int i = 0; i < 8; i++) {
            int r = ldr + i * 8;
            size_t go = (size_t)(tokBase + r) * D_MODEL + h * 64 + ldc;
            cp16(ks + r * QS_STR + ldc, K + go);
            cp16(vs + r * VS_STR + ldc, V + go);
        }
        cp_commit();
        if (tid < 64) rkb[0][tid] = rules[tokBase + tid];
    }

    const int qrow0 = qt * 64 + rbase + g;
    const int qrow1 = qrow0 + 8;

    // ---- Q fragments direct from gmem (already tf32) ----
    unsigned qa[8][4];
    {
        const float* Qr0 = Q + (size_t)(tokBase + qrow0) * D_MODEL + h * 64;
        const float* Qr1 = Q + (size_t)(tokBase + qrow1) * D_MODEL + h * 64;
#pragma unroll
        for (int kk = 0; kk < 8; kk++) {
            qa[kk][0] = __float_as_uint(Qr0[kk * 8 + tq]);
            qa[kk][1] = __float_as_uint(Qr1[kk * 8 + tq]);
            qa[kk][2] = __float_as_uint(Qr0[kk * 8 + tq + 4]);
            qa[kk][3] = __float_as_uint(Qr1[kk * 8 + tq + 4]);
        }
    }

    const unsigned long long al0 = allow[b * S_LEN + qrow0];
    const unsigned long long al1 = allow[b * S_LEN + qrow1];

    float o[8][4];
#pragma unroll
    for (int nt = 0; nt < 8; nt++)
#pragma unroll
        for (int j = 0; j < 4; j++) o[nt][j] = 0.f;
    float m0 = NEGINF, m1 = NEGINF, l0 = 0.f, l1 = 0.f;

    for (int kt = 0; kt <= qt; kt++) {
        const int buf = kt & 1;
        __syncthreads();
        if (kt < qt) {
            float* ks = ksb[buf ^ 1]; float* vs = vsb[buf ^ 1];
#pragma unroll
            for (int i = 0; i < 8; i++) {
                int r = ldr + i * 8;
                size_t go = (size_t)(tokBase + (kt + 1) * 64 + r) * D_MODEL + h * 64 + ldc;
                cp16(ks + r * QS_STR + ldc, K + go);
                cp16(vs + r * VS_STR + ldc, V + go);
            }
            cp_commit();
            if (tid < 64) rkb[buf ^ 1][tid] = rules[tokBase + (kt + 1) * 64 + tid];
            cp_wait<1>();
        } else {
            cp_wait<0>();
        }
        __syncthreads();

        const float* ks = ksb[buf];
        const float* vs = vsb[buf];
        const int*   rk_s = rkb[buf];

        // ---- S = Q K^T ----
        float s[8][4];
#pragma unroll
        for (int nt = 0; nt < 8; nt++)
#pragma unroll
            for (int j = 0; j < 4; j++) s[nt][j] = 0.f;
#pragma unroll
        for (int kk = 0; kk < 8; kk++) {
#pragma unroll
            for (int nt = 0; nt < 8; nt++) {
                unsigned b0 = __float_as_uint(ks[(nt * 8 + g) * QS_STR + kk * 8 + tq]);
                unsigned b1 = __float_as_uint(ks[(nt * 8 + g) * QS_STR + kk * 8 + tq + 4]);
                mma_tf32(s[nt], qa[kk], b0, b1);
            }
        }

        // ---- mask + scale ----
        const bool diag = (kt == qt);
#pragma unroll
        for (int nt = 0; nt < 8; nt++) {
            int c0 = nt * 8 + 2 * tq;
            int rk0 = rk_s[c0], rk1 = rk_s[c0 + 1];
            int col0 = kt * 64 + c0;
            bool ok00 = ((al0 >> rk0) & 1ULL) && (!diag || col0 <= qrow0);
            bool ok01 = ((al0 >> rk1) & 1ULL) && (!diag || col0 + 1 <= qrow0);
            bool ok10 = ((al1 >> rk0) & 1ULL) && (!diag || col0 <= qrow1);
            bool ok11 = ((al1 >> rk1) & 1ULL) && (!diag || col0 + 1 <= qrow1);
            s[nt][0] = ok00 ? s[nt][0] * 0.125f : NEGINF;
            s[nt][1] = ok01 ? s[nt][1] * 0.125f : NEGINF;
            s[nt][2] = ok10 ? s[nt][2] * 0.125f : NEGINF;
            s[nt][3] = ok11 ? s[nt][3] * 0.125f : NEGINF;
        }

        // ---- online softmax ----
        float mx0 = NEGINF, mx1 = NEGINF;
#pragma unroll
        for (int nt = 0; nt < 8; nt++) {
            mx0 = fmaxf(mx0, fmaxf(s[nt][0], s[nt][1]));
            mx1 = fmaxf(mx1, fmaxf(s[nt][2], s[nt][3]));
        }
        mx0 = fmaxf(mx0, __shfl_xor_sync(0xffffffffu, mx0, 1));
        mx0 = fmaxf(mx0, __shfl_xor_sync(0xffffffffu, mx0, 2));
        mx1 = fmaxf(mx1, __shfl_xor_sync(0xffffffffu, mx1, 1));
        mx1 = fmaxf(mx1, __shfl_xor_sync(0xffffffffu, mx1, 2));
        float mn0 = fmaxf(m0, mx0), mn1 = fmaxf(m1, mx1);
        float cr0 = (m0 == mn0) ? 1.f : __expf(m0 - mn0);
        float cr1 = (m1 == mn1) ? 1.f : __expf(m1 - mn1);
        float rs0 = 0.f, rs1 = 0.f;
        if (mn0 != NEGINF) {
#pragma unroll
            for (int nt = 0; nt < 8; nt++) {
                s[nt][0] = __expf(s[nt][0] - mn0);
                s[nt][1] = __expf(s[nt][1] - mn0);
                rs0 += s[nt][0] + s[nt][1];
            }
        } else {
#pragma unroll
            for (int nt = 0; nt < 8; nt++) { s[nt][0] = 0.f; s[nt][1] = 0.f; }
        }
        if (mn1 != NEGINF) {
#pragma unroll
            for (int nt = 0; nt < 8; nt++) {
                s[nt][2] = __expf(s[nt][2] - mn1);
                s[nt][3] = __expf(s[nt][3] - mn1);
                rs1 += s[nt][2] + s[nt][3];
            }
        } else {
#pragma unroll
            for (int nt = 0; nt < 8; nt++) { s[nt][2] = 0.f; s[nt][3] = 0.f; }
        }
        rs0 += __shfl_xor_sync(0xffffffffu, rs0, 1);
        rs0 += __shfl_xor_sync(0xffffffffu, rs0, 2);
        rs1 += __shfl_xor_sync(0xffffffffu, rs1, 1);
        rs1 += __shfl_xor_sync(0xffffffffu, rs1, 2);
        l0 = l0 * cr0 + rs0;
        l1 = l1 * cr1 + rs1;
        m0 = mn0; m1 = mn1;
#pragma unroll
        for (int nt = 0; nt < 8; nt++) {
            o[nt][0] *= cr0; o[nt][1] *= cr0;
            o[nt][2] *= cr1; o[nt][3] *= cr1;
        }

        // ---- round P to tf32 ----
#pragma unroll
        for (int nt = 0; nt < 8; nt++)
#pragma unroll
            for (int j = 0; j < 4; j++)
                s[nt][j] = __uint_as_float(f2tf(s[nt][j]));

        // ---- O += P V  (P fragments gathered via quad shuffles) ----
        const unsigned srcA = (lane & 28) | (tq >> 1);
        const unsigned srcB = srcA + 2;
        const bool odd = (tq & 1);
#pragma unroll
        for (int kk = 0; kk < 8; kk++) {
            float x0 = __shfl_sync(0xffffffffu, s[kk][0], srcA);
            float x1 = __shfl_sync(0xffffffffu, s[kk][1], srcA);
            float x2 = __shfl_sync(0xffffffffu, s[kk][2], srcA);
            float x3 = __shfl_sync(0xffffffffu, s[kk][3], srcA);
            float y0 = __shfl_sync(0xffffffffu, s[kk][0], srcB);
            float y1 = __shfl_sync(0xffffffffu, s[kk][1], srcB);
            float y2 = __shfl_sync(0xffffffffu, s[kk][2], srcB);
            float y3 = __shfl_sync(0xffffffffu, s[kk][3], srcB);
            unsigned pa[4];
            pa[0] = __float_as_uint(odd ? x1 : x0);
            pa[1] = __float_as_uint(odd ? x3 : x2);
            pa[2] = __float_as_uint(odd ? y1 : y0);
            pa[3] = __float_as_uint(odd ? y3 : y2);
#pragma unroll
            for (int nt = 0; nt < 8; nt++) {
                unsigned b0 = __float_as_uint(vs[(kk * 8 + tq) * VS_STR + nt * 8 + g]);
                unsigned b1 = __float_as_uint(vs[(kk * 8 + tq + 4) * VS_STR + nt * 8 + g]);
                mma_tf32(o[nt], pa, b0, b1);
            }
        }
    }

    float inv0 = 1.f / l0, inv1 = 1.f / l1;
#pragma unroll
    for (int nt = 0; nt < 8; nt++) {
        float2 w0 = make_float2(o[nt][0] * inv0, o[nt][1] * inv0);
        float2 w1 = make_float2(o[nt][2] * inv1, o[nt][3] * inv1);
        *(float2*)(O + (size_t)(tokBase + qrow0) * D_MODEL + h * 64 + nt * 8 + 2 * tq) = w0;
        *(float2*)(O + (size_t)(tokBase + qrow1) * D_MODEL + h * 64 + nt * 8 + 2 * tq) = w1;
    }
}

// ----------------------------------------------------------------------------
extern "C" void kernel_launch(void* const* d_in, const int* in_sizes, int n_in,
                              void* d_out, int out_size) {
    const float* x     = (const float*)d_in[0];
    const int*   rules = (const int*)  d_in[1];
    const float* q_si = (const float*)d_in[2],  *q_so = (const float*)d_in[3];
    const float* q_ri = (const float*)d_in[4],  *q_ro = (const float*)d_in[5];
    const float* q_lg = (const float*)d_in[6];
    const float* k_si = (const float*)d_in[7],  *k_so = (const float*)d_in[8];
    const float* k_ri = (const float*)d_in[9],  *k_ro = (const float*)d_in[10];
    const float* k_lg = (const float*)d_in[11];
    const float* v_si = (const float*)d_in[12], *v_so = (const float*)d_in[13];
    const float* v_ri = (const float*)d_in[14], *v_ro = (const float*)d_in[15];
    const float* v_lg = (const float*)d_in[16];
    const float* o_si = (const float*)d_in[17], *o_so = (const float*)d_in[18];
    const float* o_ri = (const float*)d_in[19], *o_ro = (const float*)d_in[20];
    const float* o_lg = (const float*)d_in[21];
    const float* router_q = (const float*)d_in[22];
    const float* router_k = (const float*)d_in[23];
    float* out = (float*)d_out;

    float *T1, *Pp, *Qb, *Kb, *Vb, *AO, *Atab;
    float2* Rope;
    unsigned long long* Allow;
    cudaGetSymbolAddress((void**)&T1,    g_T1);
    cudaGetSymbolAddress((void**)&Pp,    g_P);
    cudaGetSymbolAddress((void**)&Qb,    g_Q);
    cudaGetSymbolAddress((void**)&Kb,    g_K);
    cudaGetSymbolAddress((void**)&Vb,    g_V);
    cudaGetSymbolAddress((void**)&AO,    g_AO);
    cudaGetSymbolAddress((void**)&Atab,  g_A);
    cudaGetSymbolAddress((void**)&Allow, g_allow);
    cudaGetSymbolAddress((void**)&Rope,  g_rope);

    aff_kernel<<<16, 256>>>(router_q, router_k, Atab);
    rope_kernel<<<64, 512>>>(Rope);
    thr_allow_kernel<<<NTOK, 64>>>(rules, Atab, Allow);

    // QKV base projections (tf32 MMA, merged z, split-K)
    cudaFuncSetAttribute(gemm1_tc<3>, cudaFuncAttributeMaxDynamicSharedMemorySize, G1_SMEM);
    cudaFuncSetAttribute(gemm1_tc<1>, cudaFuncAttributeMaxDynamicSharedMemorySize, G1_SMEM);
    gemm1_tc<3><<<dim3(32, KSPLIT), 128, G1_SMEM>>>(x, q_si, k_si, v_si, Pp);
    reduce_kernel<<<(3 * NTOK * SRANK + 255) / 256, 256>>>(Pp, T1, 3);
    gemm2_kernel<<<dim3(64, 16, 3), 256>>>(T1, q_so, k_so, v_so, Qb, Kb, Vb);

    AdpArgs aq;
    aq.ri[0] = q_ri; aq.ri[1] = k_ri; aq.ri[2] = v_ri;
    aq.ro[0] = q_ro; aq.ro[1] = k_ro; aq.ro[2] = v_ro;
    aq.lg[0] = q_lg; aq.lg[1] = k_lg; aq.lg[2] = v_lg;
    aq.base[0] = Qb; aq.base[1] = Kb; aq.base[2] = Vb;
    aq.nproj = 3; aq.ropemask = 0x3; aq.tfmask = 0x7;
    adapter_kernel<<<NTOK, 128>>>(x, rules, Rope, aq);

    // flash attention (tf32 tensor cores, 64-row q-tiles, cp.async)
    cudaFuncSetAttribute(flash_tc, cudaFuncAttributeMaxDynamicSharedMemorySize, FLASH_SMEM);
    flash_tc<<<dim3(16, 64), 128, FLASH_SMEM>>>(Qb, Kb, Vb, rules, Allow, AO);

    // O projection
    gemm1_tc<1><<<dim3(32, KSPLIT), 128, G1_SMEM>>>(AO, o_si, o_si, o_si, Pp);
    reduce_kernel<<<(NTOK * SRANK + 255) / 256, 256>>>(Pp, T1, 1);
    gemm2_kernel<<<dim3(64, 16, 1), 256>>>(T1, o_so, o_so, o_so, out, out, out);

    AdpArgs ao;
    ao.ri[0] = o_ri; ao.ri[1] = o_ri; ao.ri[2] = o_ri;
    ao.ro[0] = o_ro; ao.ro[1] = o_ro; ao.ro[2] = o_ro;
    ao.lg[0] = o_lg; ao.lg[1] = o_lg; ao.lg[2] = o_lg;
    ao.base[0] = out; ao.base[1] = out; ao.base[2] = out;
    ao.nproj = 1; ao.ropemask = 0; ao.tfmask = 0;
    adapter_kernel<<<NTOK, 128>>>(AO, rules, Rope, ao);
}

// round 15
// speedup vs baseline: 2.1281x; 1.5505x over previous
#include <cuda_runtime.h>
#include <cuda_fp16.h>
#include <math.h>

#define D_MODEL 1024
#define S_LEN   1024
#define BATCH   4
#define NTOK    4096
#define NHEADS  16
#define HD      64
#define NRULES  64
#define RANK    8
#define SRANK   32
#define NBLK    16
#define TOPK    32
#define KSPLIT  4

#define NEGINF (__int_as_float(0xff800000))

// ---------------- scratch (device globals; no allocation allowed) ------------
__device__ float g_T1[3 * NTOK * SRANK];
__device__ float g_P [KSPLIT * 3 * NTOK * SRANK];
__device__ float g_Q [NTOK * D_MODEL];
__device__ float g_K [NTOK * D_MODEL];
__device__ float g_V [NTOK * D_MODEL];
__device__ __half g_Qh[NTOK * D_MODEL];
__device__ __half g_Kh[NTOK * D_MODEL];
__device__ __half g_Vh[NTOK * D_MODEL];
__device__ float g_AO[NTOK * D_MODEL];
__device__ float g_A [NRULES * NRULES];
__device__ unsigned long long g_allow[NTOK];
__device__ float2 g_rope[S_LEN * 32];

__device__ __forceinline__ unsigned f2tf(float x) {
    unsigned u;
    asm("cvt.rna.tf32.f32 %0, %1;" : "=r"(u) : "f"(x));
    return u;
}

__device__ __forceinline__ void mma_tf32(float d[4], const unsigned a[4],
                                         unsigned b0, unsigned b1) {
    asm volatile(
        "mma.sync.aligned.m16n8k8.row.col.f32.tf32.tf32.f32 "
        "{%0,%1,%2,%3}, {%4,%5,%6,%7}, {%8,%9}, {%0,%1,%2,%3};\n"
        : "+f"(d[0]), "+f"(d[1]), "+f"(d[2]), "+f"(d[3])
        : "r"(a[0]), "r"(a[1]), "r"(a[2]), "r"(a[3]), "r"(b0), "r"(b1));
}

__device__ __forceinline__ void mma_f16(float d[4], const unsigned a[4],
                                        unsigned b0, unsigned b1) {
    asm volatile(
        "mma.sync.aligned.m16n8k16.row.col.f32.f16.f16.f32 "
        "{%0,%1,%2,%3}, {%4,%5,%6,%7}, {%8,%9}, {%0,%1,%2,%3};\n"
        : "+f"(d[0]), "+f"(d[1]), "+f"(d[2]), "+f"(d[3])
        : "r"(a[0]), "r"(a[1]), "r"(a[2]), "r"(a[3]), "r"(b0), "r"(b1));
}

__device__ __forceinline__ void ldsm_x4_trans(unsigned r[4], const __half* p) {
    unsigned addr = (unsigned)__cvta_generic_to_shared(p);
    asm volatile(
        "ldmatrix.sync.aligned.m8n8.x4.trans.shared.b16 {%0,%1,%2,%3}, [%4];"
        : "=r"(r[0]), "=r"(r[1]), "=r"(r[2]), "=r"(r[3]) : "r"(addr));
}

__device__ __forceinline__ void cp16(void* smem_dst, const void* gsrc) {
    unsigned s = (unsigned)__cvta_generic_to_shared(smem_dst);
    asm volatile("cp.async.cg.shared.global [%0], [%1], 16;" :: "r"(s), "l"(gsrc));
}
__device__ __forceinline__ void cp_commit() {
    asm volatile("cp.async.commit_group;");
}
template <int N>
__device__ __forceinline__ void cp_wait() {
    asm volatile("cp.async.wait_group %0;" :: "n"(N));
}

__device__ __forceinline__ unsigned packh2(float lo, float hi) {
    __half2 h = __floats2half2_rn(lo, hi);
    return *reinterpret_cast<unsigned*>(&h);
}

// ---------------- affinity table ---------------------------------------------
__global__ void aff_kernel(const float* __restrict__ rq, const float* __restrict__ rk,
                           float* __restrict__ A) {
    int idx = blockIdx.x * blockDim.x + threadIdx.x;
    if (idx >= NRULES * NRULES) return;
    int i = idx >> 6, j = idx & 63;
    float qv[RANK], kv[RANK];
    float nq = 0.f, nk = 0.f;
#pragma unroll
    for (int r = 0; r < RANK; r++) {
        qv[r] = rq[i * RANK + r]; kv[r] = rk[j * RANK + r];
        nq += qv[r] * qv[r];      nk += kv[r] * kv[r];
    }
    float iq = 1.f / fmaxf(sqrtf(nq), 1e-12f);
    float ik = 1.f / fmaxf(sqrtf(nk), 1e-12f);
    float dot = 0.f;
#pragma unroll
    for (int r = 0; r < RANK; r++) dot += (qv[r] * iq) * (kv[r] * ik);
    A[idx] = dot * 2.0794415416798357f;
}

// ---------------- rope table --------------------------------------------------
__global__ void rope_kernel(float2* __restrict__ tab) {
    int idx = blockIdx.x * blockDim.x + threadIdx.x;
    if (idx >= S_LEN * 32) return;
    int spos = idx >> 5, i = idx & 31;
    float div = expf((float)(2 * i) * (-0.14391156831212786f)); // -ln(1e4)/64
    float ang = (float)spos * div;
    float sn, cs;
    sincosf(ang, &sn, &cs);
    tab[idx] = make_float2(cs, sn);
}

// --------- per-(b,q): top-32 threshold + allowed-rule 64-bit mask ------------
__global__ void thr_allow_kernel(const int* __restrict__ rules, const float* __restrict__ A,
                                 unsigned long long* __restrict__ allow) {
    int bq = blockIdx.x;
    int b = bq >> 10, q = bq & 1023;
    __shared__ int   cnt[NRULES];
    __shared__ float row[NRULES];
    __shared__ float thr_s;
    __shared__ unsigned bits[2];
    int t = threadIdx.x;      // 64 threads
    cnt[t] = 0;
    if (t == 0) thr_s = NEGINF;
    __syncthreads();
    const int* rb = rules + b * S_LEN;
    for (int k = t; k <= q; k += 64) atomicAdd(&cnt[rb[k]], 1);
    row[t] = A[rb[q] * NRULES + t];
    __syncthreads();
    if (q >= TOPK - 1) {
        float v = row[t];
        int   c = cnt[t];
        int greater = 0;
#pragma unroll 8
        for (int r = 0; r < NRULES; r++) greater += (row[r] > v) ? cnt[r] : 0;
        if (c > 0 && greater < TOPK && greater + c >= TOPK)
            thr_s = v;
    }
    __syncthreads();
    unsigned bal = __ballot_sync(0xffffffffu, row[t] >= thr_s);
    if ((t & 31) == 0) bits[t >> 5] = bal;
    __syncthreads();
    if (t == 0)
        allow[bq] = (unsigned long long)bits[0] | ((unsigned long long)bits[1] << 32);
}

// -------- GEMM1 (tf32 MMA, split-K, merged z): partials ----------------------
#define X_STR 36
#define B_STR 104
#define G1_SMEM ((2 * 128 * X_STR + 2 * 32 * B_STR) * 4)

template <int NZ>
__global__ void __launch_bounds__(128)
gemm1_tc(const float* __restrict__ X, const float* __restrict__ W0,
         const float* __restrict__ W1, const float* __restrict__ W2,
         float* __restrict__ P) {
    extern __shared__ float sm[];
    float* Xs = sm;                        // [2][128][36]
    float* Bs = sm + 2 * 128 * X_STR;      // [2][32][104]
    const float* Ws[3] = {W0, W1, W2};

    const int tid = threadIdx.x;
    const int warp = tid >> 5, lane = tid & 31;
    const int g = lane >> 2, tq = lane & 3;
    const int rbase = warp * 32;
    const int rowBase = blockIdx.x * 128;
    const int kBase = blockIdx.y * (D_MODEL / KSPLIT);

    float acc[2][NZ * 4][4];
#pragma unroll
    for (int a = 0; a < 2; a++)
#pragma unroll
        for (int nt = 0; nt < NZ * 4; nt++)
#pragma unroll
            for (int j = 0; j < 4; j++) acc[a][nt][j] = 0.f;

    auto stage = [&](int buf, int k0) {
        float* Xb = Xs + buf * 128 * X_STR;
#pragma unroll
        for (int i = 0; i < 8; i++) {
            int f = tid + i * 128;
            int r = f >> 3, c4 = (f & 7) * 4;
            cp16(Xb + r * X_STR + c4, X + (size_t)(rowBase + r) * D_MODEL + k0 + c4);
        }
        float* Bb = Bs + buf * 32 * B_STR;
#pragma unroll
        for (int i = 0; i < NZ * 2; i++) {
            int f = tid + i * 128;
            int k = f / (NZ * 8);
            int rem = f - k * (NZ * 8);
            int z = rem >> 3, c4 = (rem & 7) * 4;
            cp16(Bb + k * B_STR + z * 32 + c4, Ws[z] + (size_t)(k0 + k) * SRANK + c4);
        }
    };

    stage(0, kBase);
    cp_commit();

    const int nchunk = (D_MODEL / KSPLIT) / 32;   // 8
    for (int c = 0; c < nchunk; c++) {
        int buf = c & 1;
        if (c + 1 < nchunk) {
            stage(buf ^ 1, kBase + (c + 1) * 32);
            cp_commit();
            cp_wait<1>();
        } else {
            cp_wait<0>();
        }
        __syncthreads();
        const float* Xb = Xs + buf * 128 * X_STR;
        const float* Bb = Bs + buf * 32 * B_STR;
#pragma unroll
        for (int kk = 0; kk < 4; kk++) {
            unsigned a0[4], a1[4];
            a0[0] = f2tf(Xb[(rbase + g)      * X_STR + kk * 8 + tq]);
            a0[1] = f2tf(Xb[(rbase + g + 8)  * X_STR + kk * 8 + tq]);
            a0[2] = f2tf(Xb[(rbase + g)      * X_STR + kk * 8 + tq + 4]);
            a0[3] = f2tf(Xb[(rbase + g + 8)  * X_STR + kk * 8 + tq + 4]);
            a1[0] = f2tf(Xb[(rbase + g + 16) * X_STR + kk * 8 + tq]);
            a1[1] = f2tf(Xb[(rbase + g + 24) * X_STR + kk * 8 + tq]);
            a1[2] = f2tf(Xb[(rbase + g + 16) * X_STR + kk * 8 + tq + 4]);
            a1[3] = f2tf(Xb[(rbase + g + 24) * X_STR + kk * 8 + tq + 4]);
#pragma unroll
            for (int nt = 0; nt < NZ * 4; nt++) {
                unsigned b0 = f2tf(Bb[(kk * 8 + tq)     * B_STR + nt * 8 + g]);
                unsigned b1 = f2tf(Bb[(kk * 8 + tq + 4) * B_STR + nt * 8 + g]);
                mma_tf32(acc[0][nt], a0, b0, b1);
                mma_tf32(acc[1][nt], a1, b0, b1);
            }
        }
        __syncthreads();
    }

#pragma unroll
    for (int a = 0; a < 2; a++)
#pragma unroll
        for (int nt = 0; nt < NZ * 4; nt++) {
            int z = nt >> 2;
            int col = (nt & 3) * 8 + 2 * tq;
            int row0 = rowBase + rbase + a * 16 + g;
            float* dst = P + ((size_t)(blockIdx.y * 3 + z) * NTOK) * SRANK;
            *(float2*)(dst + (size_t)row0 * SRANK + col) =
                make_float2(acc[a][nt][0], acc[a][nt][1]);
            *(float2*)(dst + (size_t)(row0 + 8) * SRANK + col) =
                make_float2(acc[a][nt][2], acc[a][nt][3]);
        }
}

__global__ void reduce_kernel(const float* __restrict__ P, float* __restrict__ T, int nz) {
    int idx = blockIdx.x * blockDim.x + threadIdx.x;
    if (idx >= nz * NTOK * SRANK) return;
    int z = idx / (NTOK * SRANK);
    int off = idx - z * (NTOK * SRANK);
    float s = 0.f;
#pragma unroll
    for (int ks = 0; ks < KSPLIT; ks++)
        s += P[(size_t)(ks * 3 + z) * NTOK * SRANK + off];
    T[(size_t)z * NTOK * SRANK + off] = s;
}

// ---------------- GEMM2: C_z[4096,1024] = T[z][4096,32] * W_z[32,1024] -------
__global__ void __launch_bounds__(256)
gemm2_kernel(const float* __restrict__ T, const float* __restrict__ W0,
             const float* __restrict__ W1, const float* __restrict__ W2,
             float* __restrict__ C0, float* __restrict__ C1, float* __restrict__ C2) {
    __shared__ float As[64][36];
    __shared__ float Bt[64][36];
    int tid = threadIdx.x;
    int tx = tid & 15, ty = tid >> 4;
    int z = blockIdx.z;
    const float* W = (z == 0) ? W0 : (z == 1) ? W1 : W2;
    float* C = (z == 0) ? C0 : (z == 1) ? C1 : C2;
    const float* A = T + (size_t)z * NTOK * SRANK;
    int rowBase = blockIdx.x * 64, colBase = blockIdx.y * 64;

#pragma unroll
    for (int i = 0; i < 2; i++) {
        int f = tid + i * 256;
        int r = f >> 3, kq = f & 7;
        float4 v = *(const float4*)(A + (size_t)(rowBase + r) * SRANK + kq * 4);
        *(float4*)&As[r][kq * 4] = v;
    }
#pragma unroll
    for (int i = 0; i < 8; i++) {
        int f = tid + i * 256;
        int k = f >> 6, c = f & 63;
        Bt[c][k] = W[(size_t)k * D_MODEL + colBase + c];
    }
    __syncthreads();

    float acc[4][4];
#pragma unroll
    for (int i = 0; i < 4; i++)
#pragma unroll
        for (int j = 0; j < 4; j++) acc[i][j] = 0.f;
#pragma unroll
    for (int kq = 0; kq < 8; kq++) {
        float4 a[4], bb[4];
#pragma unroll
        for (int i = 0; i < 4; i++) a[i]  = *(float4*)&As[ty + 16 * i][kq * 4];
#pragma unroll
        for (int j = 0; j < 4; j++) bb[j] = *(float4*)&Bt[tx + 16 * j][kq * 4];
#pragma unroll
        for (int i = 0; i < 4; i++)
#pragma unroll
            for (int j = 0; j < 4; j++)
                acc[i][j] += a[i].x * bb[j].x + a[i].y * bb[j].y
                           + a[i].z * bb[j].z + a[i].w * bb[j].w;
    }
#pragma unroll
    for (int i = 0; i < 4; i++)
#pragma unroll
        for (int j = 0; j < 4; j++)
            C[(size_t)(rowBase + ty + 16 * i) * D_MODEL + colBase + tx + 16 * j] = acc[i][j];
}

// -------- adapters (up to 3 projections per block, sharing the x load) -------
struct AdpArgs {
    const float* ri[3];
    const float* ro[3];
    const float* lg[3];
    float*       base[3];
    __half*      hb[3];
    int nproj;
    int ropemask;
    int hmask;       // projections whose output goes to fp16 buffer (no fp32 write)
};

__global__ void __launch_bounds__(128)
adapter_kernel(const float* __restrict__ X, const int* __restrict__ rules,
               const float2* __restrict__ rope, AdpArgs A) {
    __shared__ float xs[D_MODEL];
    __shared__ float ris[HD * RANK];
    __shared__ float ros[RANK * HD];
    __shared__ float hs[NBLK * RANK];
    __shared__ float sels[NBLK];
    int n = blockIdx.x;
    int t = threadIdx.x;
    int rule = rules[n];

    const float4* x4 = (const float4*)(X + (size_t)n * D_MODEL);
    float4* xs4 = (float4*)xs;
    xs4[t] = x4[t];
    xs4[t + 128] = x4[t + 128];

    int spos = n & (S_LEN - 1);
    int d0 = t * 8;
    int dh0 = d0 & 63;
    int blk = t >> 3;

    for (int p = 0; p < A.nproj; p++) {
#pragma unroll
        for (int i = 0; i < 4; i++) {
            ris[t + i * 128] = A.ri[p][rule * 512 + t + i * 128];
            ros[t + i * 128] = A.ro[p][rule * 512 + t + i * 128];
        }
        if (t < 32) {
            int j = t & 15;
            float v = A.lg[p][rule * NBLK + j] * 4.0f;
            float mx = v;
#pragma unroll
            for (int msk = 8; msk >= 1; msk >>= 1)
                mx = fmaxf(mx, __shfl_xor_sync(0xffffffffu, mx, msk));
            float e = expf(v - mx);
            float sm2 = e;
#pragma unroll
            for (int msk = 8; msk >= 1; msk >>= 1)
                sm2 += __shfl_xor_sync(0xffffffffu, sm2, msk);
            if (t < 16) sels[t] = e / sm2;
        }
        __syncthreads();
        {
            int bb = t >> 3, r = t & 7;
            float sum = 0.f;
#pragma unroll
            for (int sx = 0; sx < 64; sx++) sum += xs[bb * 64 + sx] * ris[sx * 8 + r];
            hs[t] = sum;
        }
        __syncthreads();
        float hl[8];
#pragma unroll
        for (int r = 0; r < 8; r++) hl[r] = hs[blk * 8 + r];
        float selv = sels[blk];
        float* Base = A.base[p];
        float4 b0 = *(float4*)(Base + (size_t)n * D_MODEL + d0);
        float4 b1 = *(float4*)(Base + (size_t)n * D_MODEL + d0 + 4);
        float outv[8] = {b0.x, b0.y, b0.z, b0.w, b1.x, b1.y, b1.z, b1.w};
        float av[8] = {0.f, 0.f, 0.f, 0.f, 0.f, 0.f, 0.f, 0.f};
#pragma unroll
        for (int r = 0; r < 8; r++) {
            float4 r0 = *(float4*)&ros[r * 64 + dh0];
            float4 r1 = *(float4*)&ros[r * 64 + dh0 + 4];
            av[0] += hl[r] * r0.x; av[1] += hl[r] * r0.y;
            av[2] += hl[r] * r0.z; av[3] += hl[r] * r0.w;
            av[4] += hl[r] * r1.x; av[5] += hl[r] * r1.y;
            av[6] += hl[r] * r1.z; av[7] += hl[r] * r1.w;
        }
#pragma unroll
        for (int c = 0; c < 8; c++) outv[c] += av[c] * selv;
        if ((A.ropemask >> p) & 1) {
#pragma unroll
            for (int pp = 0; pp < 4; pp++) {
                int i = (dh0 + 2 * pp) >> 1;
                float2 cs = __ldg(&rope[spos * 32 + i]);
                float t1 = outv[2 * pp], t2 = outv[2 * pp + 1];
                outv[2 * pp]     = t1 * cs.x - t2 * cs.y;
                outv[2 * pp + 1] = t2 * cs.x + t1 * cs.y;
            }
        }
        if ((A.hmask >> p) & 1) {
            __half* H = A.hb[p] + (size_t)n * D_MODEL + d0;
#pragma unroll
            for (int c = 0; c < 8; c += 2)
                *(__half2*)(H + c) = __floats2half2_rn(outv[c], outv[c + 1]);
        } else {
            *(float4*)(Base + (size_t)n * D_MODEL + d0)     = make_float4(outv[0], outv[1], outv[2], outv[3]);
            *(float4*)(Base + (size_t)n * D_MODEL + d0 + 4) = make_float4(outv[4], outv[5], outv[6], outv[7]);
        }
        __syncthreads();
    }
}

// ------------------------- flash attention (fp16 MMA) ------------------------
// K/V fp16 in smem [key][72] (144B rows). K B-frags: conflict-free LDS.32 of
// half2 pairs. V B-frags: ldmatrix.x4.trans. P reuses the S accumulator layout
// as the fp16 A-fragment (no shuffles).
#define KV_STR 72
#define FLASH_SMEM (4 * 64 * KV_STR * 2 + 2 * 64 * 4)

__global__ void __launch_bounds__(128)
flash_tc(const __half* __restrict__ Q, const __half* __restrict__ K,
         const __half* __restrict__ V, const int* __restrict__ rules,
         const unsigned long long* __restrict__ allow, float* __restrict__ O) {
    extern __shared__ __half smh[];
    __half* ksb[2]; __half* vsb[2]; int* rkb[2];
    ksb[0] = smh;
    ksb[1] = ksb[0] + 64 * KV_STR;
    vsb[0] = ksb[1] + 64 * KV_STR;
    vsb[1] = vsb[0] + 64 * KV_STR;
    rkb[0] = (int*)(vsb[1] + 64 * KV_STR);
    rkb[1] = rkb[0] + 64;

    const int tid  = threadIdx.x;
    const int lane = tid & 31;
    const int warp = tid >> 5;
    const int g = lane >> 2, tq = lane & 3;
    const int qt = gridDim.x - 1 - blockIdx.x;     // heavy blocks first
    const int b = blockIdx.y >> 4, h = blockIdx.y & 15;
    const int tokBase = b * S_LEN;
    const int rbase = warp * 16;

    auto load_tile = [&](int buf, int kt) {
        __half* ks = ksb[buf]; __half* vs = vsb[buf];
#pragma unroll
        for (int i = 0; i < 4; i++) {
            int f = tid + i * 128;
            int key = f >> 3, ch = f & 7;
            size_t go = (size_t)(tokBase + kt * 64 + key) * D_MODEL + h * 64 + ch * 8;
            cp16(ks + key * KV_STR + ch * 8, K + go);
            cp16(vs + key * KV_STR + ch * 8, V + go);
        }
    };

    load_tile(0, 0);
    cp_commit();
    if (tid < 64) rkb[0][tid] = rules[tokBase + tid];

    const int qrow0 = qt * 64 + rbase + g;
    const int qrow1 = qrow0 + 8;

    // ---- Q A-fragments direct from gmem (fp16, packed pairs) ----
    unsigned qa[4][4];
    {
        const __half* Qr0 = Q + (size_t)(tokBase + qrow0) * D_MODEL + h * 64;
        const __half* Qr1 = Q + (size_t)(tokBase + qrow1) * D_MODEL + h * 64;
#pragma unroll
        for (int kk = 0; kk < 4; kk++) {
            qa[kk][0] = *(const unsigned*)(Qr0 + kk * 16 + 2 * tq);
            qa[kk][1] = *(const unsigned*)(Qr1 + kk * 16 + 2 * tq);
            qa[kk][2] = *(const unsigned*)(Qr0 + kk * 16 + 2 * tq + 8);
            qa[kk][3] = *(const unsigned*)(Qr1 + kk * 16 + 2 * tq + 8);
        }
    }

    const unsigned long long al0 = allow[b * S_LEN + qrow0];
    const unsigned long long al1 = allow[b * S_LEN + qrow1];

    float o[8][4];
#pragma unroll
    for (int nt = 0; nt < 8; nt++)
#pragma unroll
        for (int j = 0; j < 4; j++) o[nt][j] = 0.f;
    float m0 = NEGINF, m1 = NEGINF, l0 = 0.f, l1 = 0.f;

    for (int kt = 0; kt <= qt; kt++) {
        const int buf = kt & 1;
        __syncthreads();
        if (kt < qt) {
            load_tile(buf ^ 1, kt + 1);
            cp_commit();
            if (tid < 64) rkb[buf ^ 1][tid] = rules[tokBase + (kt + 1) * 64 + tid];
            cp_wait<1>();
        } else {
            cp_wait<0>();
        }
        __syncthreads();

        const __half* ks = ksb[buf];
        const __half* vs = vsb[buf];
        const int*    rk_s = rkb[buf];

        // ---- S = Q K^T (fp16 m16n8k16) ----
        float s[8][4];
#pragma unroll
        for (int nt = 0; nt < 8; nt++)
#pragma unroll
            for (int j = 0; j < 4; j++) s[nt][j] = 0.f;
#pragma unroll
        for (int kk = 0; kk < 4; kk++) {
#pragma unroll
            for (int nt = 0; nt < 8; nt++) {
                const __half* kp = ks + (nt * 8 + g) * KV_STR + kk * 16 + 2 * tq;
                unsigned b0 = *(const unsigned*)kp;
                unsigned b1 = *(const unsigned*)(kp + 8);
                mma_f16(s[nt], qa[kk], b0, b1);
            }
        }

        // ---- mask + scale ----
        const bool diag = (kt == qt);
#pragma unroll
        for (int nt = 0; nt < 8; nt++) {
            int c0 = nt * 8 + 2 * tq;
            int rk0 = rk_s[c0], rk1 = rk_s[c0 + 1];
            int col0 = kt * 64 + c0;
            bool ok00 = ((al0 >> rk0) & 1ULL) && (!diag || col0 <= qrow0);
            bool ok01 = ((al0 >> rk1) & 1ULL) && (!diag || col0 + 1 <= qrow0);
            bool ok10 = ((al1 >> rk0) & 1ULL) && (!diag || col0 <= qrow1);
            bool ok11 = ((al1 >> rk1) & 1ULL) && (!diag || col0 + 1 <= qrow1);
            s[nt][0] = ok00 ? s[nt][0] * 0.125f : NEGINF;
            s[nt][1] = ok01 ? s[nt][1] * 0.125f : NEGINF;
            s[nt][2] = ok10 ? s[nt][2] * 0.125f : NEGINF;
            s[nt][3] = ok11 ? s[nt][3] * 0.125f : NEGINF;
        }

        // ---- online softmax ----
        float mx0 = NEGINF, mx1 = NEGINF;
#pragma unroll
        for (int nt = 0; nt < 8; nt++) {
            mx0 = fmaxf(mx0, fmaxf(s[nt][0], s[nt][1]));
            mx1 = fmaxf(mx1, fmaxf(s[nt][2], s[nt][3]));
        }
        mx0 = fmaxf(mx0, __shfl_xor_sync(0xffffffffu, mx0, 1));
        mx0 = fmaxf(mx0, __shfl_xor_sync(0xffffffffu, mx0, 2));
        mx1 = fmaxf(mx1, __shfl_xor_sync(0xffffffffu, mx1, 1));
        mx1 = fmaxf(mx1, __shfl_xor_sync(0xffffffffu, mx1, 2));
        float mn0 = fmaxf(m0, mx0), mn1 = fmaxf(m1, mx1);
        float cr0 = (m0 == mn0) ? 1.f : __expf(m0 - mn0);
        float cr1 = (m1 == mn1) ? 1.f : __expf(m1 - mn1);
        float rs0 = 0.f, rs1 = 0.f;
        if (mn0 != NEGINF) {
#pragma unroll
            for (int nt = 0; nt < 8; nt++) {
                s[nt][0] = __expf(s[nt][0] - mn0);
                s[nt][1] = __expf(s[nt][1] - mn0);
                rs0 += s[nt][0] + s[nt][1];
            }
        } else {
#pragma unroll
            for (int nt = 0; nt < 8; nt++) { s[nt][0] = 0.f; s[nt][1] = 0.f; }
        }
        if (mn1 != NEGINF) {
#pragma unroll
            for (int nt = 0; nt < 8; nt++) {
                s[nt][2] = __expf(s[nt][2] - mn1);
                s[nt][3] = __expf(s[nt][3] - mn1);
                rs1 += s[nt][2] + s[nt][3];
            }
        } else {
#pragma unroll
            for (int nt = 0; nt < 8; nt++) { s[nt][2] = 0.f; s[nt][3] = 0.f; }
        }
        rs0 += __shfl_xor_sync(0xffffffffu, rs0, 1);
        rs0 += __shfl_xor_sync(0xffffffffu, rs0, 2);
        rs1 += __shfl_xor_sync(0xffffffffu, rs1, 1);
        rs1 += __shfl_xor_sync(0xffffffffu, rs1, 2);
        l0 = l0 * cr0 + rs0;
        l1 = l1 * cr1 + rs1;
        m0 = mn0; m1 = mn1;
#pragma unroll
        for (int nt = 0; nt < 8; nt++) {
            o[nt][0] *= cr0; o[nt][1] *= cr0;
            o[nt][2] *= cr1; o[nt][3] *= cr1;
        }

        // ---- O += P V : P packs straight from S accumulators (fp16 A layout) ----
#pragma unroll
        for (int kk = 0; kk < 4; kk++) {
            unsigned pa[4];
            pa[0] = packh2(s[2 * kk][0],     s[2 * kk][1]);
            pa[1] = packh2(s[2 * kk][2],     s[2 * kk][3]);
            pa[2] = packh2(s[2 * kk + 1][0], s[2 * kk + 1][1]);
            pa[3] = packh2(s[2 * kk + 1][2], s[2 * kk + 1][3]);
#pragma unroll
            for (int ntp = 0; ntp < 4; ntp++) {
                int mtx = lane >> 3;
                int key = kk * 16 + (mtx & 1) * 8 + (lane & 7);
                int d   = ntp * 16 + (mtx >> 1) * 8;
                unsigned r[4];
                ldsm_x4_trans(r, vs + key * KV_STR + d);
                mma_f16(o[2 * ntp],     pa, r[0], r[1]);
                mma_f16(o[2 * ntp + 1], pa, r[2], r[3]);
            }
        }
    }

    float inv0 = 1.f / l0, inv1 = 1.f / l1;
#pragma unroll
    for (int nt = 0; nt < 8; nt++) {
        float2 w0 = make_float2(o[nt][0] * inv0, o[nt][1] * inv0);
        float2 w1 = make_float2(o[nt][2] * inv1, o[nt][3] * inv1);
        *(float2*)(O + (size_t)(tokBase + qrow0) * D_MODEL + h * 64 + nt * 8 + 2 * tq) = w0;
        *(float2*)(O + (size_t)(tokBase + qrow1) * D_MODEL + h * 64 + nt * 8 + 2 * tq) = w1;
    }
}

// ----------------------------------------------------------------------------
extern "C" void kernel_launch(void* const* d_in, const int* in_sizes, int n_in,
                              void* d_out, int out_size) {
    const float* x     = (const float*)d_in[0];
    const int*   rules = (const int*)  d_in[1];
    const float* q_si = (const float*)d_in[2],  *q_so = (const float*)d_in[3];
    const float* q_ri = (const float*)d_in[4],  *q_ro = (const float*)d_in[5];
    const float* q_lg = (const float*)d_in[6];
    const float* k_si = (const float*)d_in[7],  *k_so = (const float*)d_in[8];
    const float* k_ri = (const float*)d_in[9],  *k_ro = (const float*)d_in[10];
    const float* k_lg = (const float*)d_in[11];
    const float* v_si = (const float*)d_in[12], *v_so = (const float*)d_in[13];
    const float* v_ri = (const float*)d_in[14], *v_ro = (const float*)d_in[15];
    const float* v_lg = (const float*)d_in[16];
    const float* o_si = (const float*)d_in[17], *o_so = (const float*)d_in[18];
    const float* o_ri = (const float*)d_in[19], *o_ro = (const float*)d_in[20];
    const float* o_lg = (const float*)d_in[21];
    const float* router_q = (const float*)d_in[22];
    const float* router_k = (const float*)d_in[23];
    float* out = (float*)d_out;

    float *T1, *Pp, *Qb, *Kb, *Vb, *AO, *Atab;
    __half *Qh, *Kh, *Vh;
    float2* Rope;
    unsigned long long* Allow;
    cudaGetSymbolAddress((void**)&T1,    g_T1);
    cudaGetSymbolAddress((void**)&Pp,    g_P);
    cudaGetSymbolAddress((void**)&Qb,    g_Q);
    cudaGetSymbolAddress((void**)&Kb,    g_K);
    cudaGetSymbolAddress((void**)&Vb,    g_V);
    cudaGetSymbolAddress((void**)&Qh,    g_Qh);
    cudaGetSymbolAddress((void**)&Kh,    g_Kh);
    cudaGetSymbolAddress((void**)&Vh,    g_Vh);
    cudaGetSymbolAddress((void**)&AO,    g_AO);
    cudaGetSymbolAddress((void**)&Atab,  g_A);
    cudaGetSymbolAddress((void**)&Allow, g_allow);
    cudaGetSymbolAddress((void**)&Rope,  g_rope);

    aff_kernel<<<16, 256>>>(router_q, router_k, Atab);
    rope_kernel<<<64, 512>>>(Rope);
    thr_allow_kernel<<<NTOK, 64>>>(rules, Atab, Allow);

    // QKV base projections (tf32 MMA, merged z, split-K)
    cudaFuncSetAttribute(gemm1_tc<3>, cudaFuncAttributeMaxDynamicSharedMemorySize, G1_SMEM);
    cudaFuncSetAttribute(gemm1_tc<1>, cudaFuncAttributeMaxDynamicSharedMemorySize, G1_SMEM);
    gemm1_tc<3><<<dim3(32, KSPLIT), 128, G1_SMEM>>>(x, q_si, k_si, v_si, Pp);
    reduce_kernel<<<(3 * NTOK * SRANK + 255) / 256, 256>>>(Pp, T1, 3);
    gemm2_kernel<<<dim3(64, 16, 3), 256>>>(T1, q_so, k_so, v_so, Qb, Kb, Vb);

    AdpArgs aq;
    aq.ri[0] = q_ri; aq.ri[1] = k_ri; aq.ri[2] = v_ri;
    aq.ro[0] = q_ro; aq.ro[1] = k_ro; aq.ro[2] = v_ro;
    aq.lg[0] = q_lg; aq.lg[1] = k_lg; aq.lg[2] = v_lg;
    aq.base[0] = Qb; aq.base[1] = Kb; aq.base[2] = Vb;
    aq.hb[0] = Qh;  aq.hb[1] = Kh;  aq.hb[2] = Vh;
    aq.nproj = 3; aq.ropemask = 0x3; aq.hmask = 0x7;
    adapter_kernel<<<NTOK, 128>>>(x, rules, Rope, aq);

    // flash attention (fp16 tensor cores, 64-row q-tiles, cp.async)
    cudaFuncSetAttribute(flash_tc, cudaFuncAttributeMaxDynamicSharedMemorySize, FLASH_SMEM);
    flash_tc<<<dim3(16, 64), 128, FLASH_SMEM>>>(Qh, Kh, Vh, rules, Allow, AO);

    // O projection
    gemm1_tc<1><<<dim3(32, KSPLIT), 128, G1_SMEM>>>(AO, o_si, o_si, o_si, Pp);
    reduce_kernel<<<(NTOK * SRANK + 255) / 256, 256>>>(Pp, T1, 1);
    gemm2_kernel<<<dim3(64, 16, 1), 256>>>(T1, o_so, o_so, o_so, out, out, out);

    AdpArgs ao;
    ao.ri[0] = o_ri; ao.ri[1] = o_ri; ao.ri[2] = o_ri;
    ao.ro[0] = o_ro; ao.ro[1] = o_ro; ao.ro[2] = o_ro;
    ao.lg[0] = o_lg; ao.lg[1] = o_lg; ao.lg[2] = o_lg;
    ao.base[0] = out; ao.base[1] = out; ao.base[2] = out;
    ao.hb[0] = 0; ao.hb[1] = 0; ao.hb[2] = 0;
    ao.nproj = 1; ao.ropemask = 0; ao.hmask = 0;
    adapter_kernel<<<NTOK, 128>>>(AO, rules, Rope, ao);
}

// round 16
// speedup vs baseline: 2.2831x; 1.0728x over previous
#include <cuda_runtime.h>
#include <cuda_fp16.h>
#include <math.h>

#define D_MODEL 1024
#define S_LEN   1024
#define BATCH   4
#define NTOK    4096
#define NHEADS  16
#define HD      64
#define NRULES  64
#define RANK    8
#define SRANK   32
#define NBLK    16
#define TOPK    32
#define KSPLIT  4

#define NEGINF (__int_as_float(0xff800000))

// ---------------- scratch (device globals; no allocation allowed) ------------
__device__ float g_T1[3 * NTOK * SRANK];
__device__ float g_P [KSPLIT * 3 * NTOK * SRANK];
__device__ float g_Q [NTOK * D_MODEL];
__device__ float g_K [NTOK * D_MODEL];
__device__ float g_V [NTOK * D_MODEL];
__device__ __half g_Qh[NTOK * D_MODEL];
__device__ __half g_Kh[NTOK * D_MODEL];
__device__ __half g_Vh[NTOK * D_MODEL];
__device__ float g_AO[NTOK * D_MODEL];
__device__ float g_A [NRULES * NRULES];
__device__ unsigned long long g_allow[NTOK];
__device__ float2 g_rope[S_LEN * 32];

__device__ __forceinline__ unsigned f2tf(float x) {
    unsigned u;
    asm("cvt.rna.tf32.f32 %0, %1;" : "=r"(u) : "f"(x));
    return u;
}

__device__ __forceinline__ void mma_tf32(float d[4], const unsigned a[4],
                                         unsigned b0, unsigned b1) {
    asm volatile(
        "mma.sync.aligned.m16n8k8.row.col.f32.tf32.tf32.f32 "
        "{%0,%1,%2,%3}, {%4,%5,%6,%7}, {%8,%9}, {%0,%1,%2,%3};\n"
        : "+f"(d[0]), "+f"(d[1]), "+f"(d[2]), "+f"(d[3])
        : "r"(a[0]), "r"(a[1]), "r"(a[2]), "r"(a[3]), "r"(b0), "r"(b1));
}

__device__ __forceinline__ void mma_f16(float d[4], const unsigned a[4],
                                        unsigned b0, unsigned b1) {
    asm volatile(
        "mma.sync.aligned.m16n8k16.row.col.f32.f16.f16.f32 "
        "{%0,%1,%2,%3}, {%4,%5,%6,%7}, {%8,%9}, {%0,%1,%2,%3};\n"
        : "+f"(d[0]), "+f"(d[1]), "+f"(d[2]), "+f"(d[3])
        : "r"(a[0]), "r"(a[1]), "r"(a[2]), "r"(a[3]), "r"(b0), "r"(b1));
}

__device__ __forceinline__ void ldsm_x4_trans(unsigned r[4], const __half* p) {
    unsigned addr = (unsigned)__cvta_generic_to_shared(p);
    asm volatile(
        "ldmatrix.sync.aligned.m8n8.x4.trans.shared.b16 {%0,%1,%2,%3}, [%4];"
        : "=r"(r[0]), "=r"(r[1]), "=r"(r[2]), "=r"(r[3]) : "r"(addr));
}

__device__ __forceinline__ void cp16(void* smem_dst, const void* gsrc) {
    unsigned s = (unsigned)__cvta_generic_to_shared(smem_dst);
    asm volatile("cp.async.cg.shared.global [%0], [%1], 16;" :: "r"(s), "l"(gsrc));
}
__device__ __forceinline__ void cp_commit() {
    asm volatile("cp.async.commit_group;");
}
template <int N>
__device__ __forceinline__ void cp_wait() {
    asm volatile("cp.async.wait_group %0;" :: "n"(N));
}

__device__ __forceinline__ unsigned packh2(float lo, float hi) {
    __half2 h = __floats2half2_rn(lo, hi);
    return *reinterpret_cast<unsigned*>(&h);
}

// ---------------- affinity table ---------------------------------------------
__global__ void aff_kernel(const float* __restrict__ rq, const float* __restrict__ rk,
                           float* __restrict__ A) {
    int idx = blockIdx.x * blockDim.x + threadIdx.x;
    if (idx >= NRULES * NRULES) return;
    int i = idx >> 6, j = idx & 63;
    float qv[RANK], kv[RANK];
    float nq = 0.f, nk = 0.f;
#pragma unroll
    for (int r = 0; r < RANK; r++) {
        qv[r] = rq[i * RANK + r]; kv[r] = rk[j * RANK + r];
        nq += qv[r] * qv[r];      nk += kv[r] * kv[r];
    }
    float iq = 1.f / fmaxf(sqrtf(nq), 1e-12f);
    float ik = 1.f / fmaxf(sqrtf(nk), 1e-12f);
    float dot = 0.f;
#pragma unroll
    for (int r = 0; r < RANK; r++) dot += (qv[r] * iq) * (kv[r] * ik);
    A[idx] = dot * 2.0794415416798357f;
}

// ---------------- rope table --------------------------------------------------
__global__ void rope_kernel(float2* __restrict__ tab) {
    int idx = blockIdx.x * blockDim.x + threadIdx.x;
    if (idx >= S_LEN * 32) return;
    int spos = idx >> 5, i = idx & 31;
    float div = expf((float)(2 * i) * (-0.14391156831212786f)); // -ln(1e4)/64
    float ang = (float)spos * div;
    float sn, cs;
    sincosf(ang, &sn, &cs);
    tab[idx] = make_float2(cs, sn);
}

// --------- per-(b,q): top-32 threshold + allowed-rule 64-bit mask ------------
__global__ void thr_allow_kernel(const int* __restrict__ rules, const float* __restrict__ A,
                                 unsigned long long* __restrict__ allow) {
    int bq = blockIdx.x;
    int b = bq >> 10, q = bq & 1023;
    __shared__ int   cnt[NRULES];
    __shared__ float row[NRULES];
    __shared__ float thr_s;
    __shared__ unsigned bits[2];
    int t = threadIdx.x;      // 64 threads
    cnt[t] = 0;
    if (t == 0) thr_s = NEGINF;
    __syncthreads();
    const int* rb = rules + b * S_LEN;
    for (int k = t; k <= q; k += 64) atomicAdd(&cnt[rb[k]], 1);
    row[t] = A[rb[q] * NRULES + t];
    __syncthreads();
    if (q >= TOPK - 1) {
        float v = row[t];
        int   c = cnt[t];
        int greater = 0;
#pragma unroll 8
        for (int r = 0; r < NRULES; r++) greater += (row[r] > v) ? cnt[r] : 0;
        if (c > 0 && greater < TOPK && greater + c >= TOPK)
            thr_s = v;
    }
    __syncthreads();
    unsigned bal = __ballot_sync(0xffffffffu, row[t] >= thr_s);
    if ((t & 31) == 0) bits[t >> 5] = bal;
    __syncthreads();
    if (t == 0)
        allow[bq] = (unsigned long long)bits[0] | ((unsigned long long)bits[1] << 32);
}

// -------- GEMM1 (tf32 MMA, split-K, merged z): partials ----------------------
#define X_STR 36
#define B_STR 104
#define G1_SMEM ((2 * 128 * X_STR + 2 * 32 * B_STR) * 4)

template <int NZ>
__global__ void __launch_bounds__(128)
gemm1_tc(const float* __restrict__ X, const float* __restrict__ W0,
         const float* __restrict__ W1, const float* __restrict__ W2,
         float* __restrict__ P) {
    extern __shared__ float sm[];
    float* Xs = sm;                        // [2][128][36]
    float* Bs = sm + 2 * 128 * X_STR;      // [2][32][104]
    const float* Ws[3] = {W0, W1, W2};

    const int tid = threadIdx.x;
    const int warp = tid >> 5, lane = tid & 31;
    const int g = lane >> 2, tq = lane & 3;
    const int rbase = warp * 32;
    const int rowBase = blockIdx.x * 128;
    const int kBase = blockIdx.y * (D_MODEL / KSPLIT);

    float acc[2][NZ * 4][4];
#pragma unroll
    for (int a = 0; a < 2; a++)
#pragma unroll
        for (int nt = 0; nt < NZ * 4; nt++)
#pragma unroll
            for (int j = 0; j < 4; j++) acc[a][nt][j] = 0.f;

    auto stage = [&](int buf, int k0) {
        float* Xb = Xs + buf * 128 * X_STR;
#pragma unroll
        for (int i = 0; i < 8; i++) {
            int f = tid + i * 128;
            int r = f >> 3, c4 = (f & 7) * 4;
            cp16(Xb + r * X_STR + c4, X + (size_t)(rowBase + r) * D_MODEL + k0 + c4);
        }
        float* Bb = Bs + buf * 32 * B_STR;
#pragma unroll
        for (int i = 0; i < NZ * 2; i++) {
            int f = tid + i * 128;
            int k = f / (NZ * 8);
            int rem = f - k * (NZ * 8);
            int z = rem >> 3, c4 = (rem & 7) * 4;
            cp16(Bb + k * B_STR + z * 32 + c4, Ws[z] + (size_t)(k0 + k) * SRANK + c4);
        }
    };

    stage(0, kBase);
    cp_commit();

    const int nchunk = (D_MODEL / KSPLIT) / 32;   // 8
    for (int c = 0; c < nchunk; c++) {
        int buf = c & 1;
        if (c + 1 < nchunk) {
            stage(buf ^ 1, kBase + (c + 1) * 32);
            cp_commit();
            cp_wait<1>();
        } else {
            cp_wait<0>();
        }
        __syncthreads();
        const float* Xb = Xs + buf * 128 * X_STR;
        const float* Bb = Bs + buf * 32 * B_STR;
#pragma unroll
        for (int kk = 0; kk < 4; kk++) {
            unsigned a0[4], a1[4];
            a0[0] = f2tf(Xb[(rbase + g)      * X_STR + kk * 8 + tq]);
            a0[1] = f2tf(Xb[(rbase + g + 8)  * X_STR + kk * 8 + tq]);
            a0[2] = f2tf(Xb[(rbase + g)      * X_STR + kk * 8 + tq + 4]);
            a0[3] = f2tf(Xb[(rbase + g + 8)  * X_STR + kk * 8 + tq + 4]);
            a1[0] = f2tf(Xb[(rbase + g + 16) * X_STR + kk * 8 + tq]);
            a1[1] = f2tf(Xb[(rbase + g + 24) * X_STR + kk * 8 + tq]);
            a1[2] = f2tf(Xb[(rbase + g + 16) * X_STR + kk * 8 + tq + 4]);
            a1[3] = f2tf(Xb[(rbase + g + 24) * X_STR + kk * 8 + tq + 4]);
#pragma unroll
            for (int nt = 0; nt < NZ * 4; nt++) {
                unsigned b0 = f2tf(Bb[(kk * 8 + tq)     * B_STR + nt * 8 + g]);
                unsigned b1 = f2tf(Bb[(kk * 8 + tq + 4) * B_STR + nt * 8 + g]);
                mma_tf32(acc[0][nt], a0, b0, b1);
                mma_tf32(acc[1][nt], a1, b0, b1);
            }
        }
        __syncthreads();
    }

#pragma unroll
    for (int a = 0; a < 2; a++)
#pragma unroll
        for (int nt = 0; nt < NZ * 4; nt++) {
            int z = nt >> 2;
            int col = (nt & 3) * 8 + 2 * tq;
            int row0 = rowBase + rbase + a * 16 + g;
            float* dst = P + ((size_t)(blockIdx.y * 3 + z) * NTOK) * SRANK;
            *(float2*)(dst + (size_t)row0 * SRANK + col) =
                make_float2(acc[a][nt][0], acc[a][nt][1]);
            *(float2*)(dst + (size_t)(row0 + 8) * SRANK + col) =
                make_float2(acc[a][nt][2], acc[a][nt][3]);
        }
}

// ---- GEMM2 (tf32 MMA): C_z[4096,1024] = (Σ_ks P[ks][z]) [4096,32] @ W_z -----
// Split-K reduction of gemm1's partials is fused into the A-tile load.
__global__ void __launch_bounds__(128)
gemm2_tc(const float* __restrict__ P, const float* __restrict__ W0,
         const float* __restrict__ W1, const float* __restrict__ W2,
         float* __restrict__ C0, float* __restrict__ C1, float* __restrict__ C2) {
    __shared__ float Ts[64][36];
    __shared__ float Wsm[32][72];
    const int tid = threadIdx.x;
    const int warp = tid >> 5, lane = tid & 31;
    const int g = lane >> 2, tq = lane & 3;
    const int z = blockIdx.z;
    const float* W = (z == 0) ? W0 : (z == 1) ? W1 : W2;
    float* C = (z == 0) ? C0 : (z == 1) ? C1 : C2;
    const int rowBase = blockIdx.x * 64, colBase = blockIdx.y * 64;

    // A tile: sum 4 split-K partials (64x32 = 512 float4, 128 thr -> 4 each)
#pragma unroll
    for (int i = 0; i < 4; i++) {
        int f = tid + i * 128;
        int r = f >> 3, c4 = (f & 7) * 4;
        size_t off = (size_t)(rowBase + r) * SRANK + c4;
        float4 v0 = *(const float4*)(P + (size_t)(0 * 3 + z) * NTOK * SRANK + off);
        float4 v1 = *(const float4*)(P + (size_t)(1 * 3 + z) * NTOK * SRANK + off);
        float4 v2 = *(const float4*)(P + (size_t)(2 * 3 + z) * NTOK * SRANK + off);
        float4 v3 = *(const float4*)(P + (size_t)(3 * 3 + z) * NTOK * SRANK + off);
        float4 s;
        s.x = v0.x + v1.x + v2.x + v3.x;
        s.y = v0.y + v1.y + v2.y + v3.y;
        s.z = v0.z + v1.z + v2.z + v3.z;
        s.w = v0.w + v1.w + v2.w + v3.w;
        *(float4*)&Ts[r][c4] = s;
    }
    // W tile: 32x64 (512 float4)
#pragma unroll
    for (int i = 0; i < 4; i++) {
        int f = tid + i * 128;
        int k = f >> 4, c4 = (f & 15) * 4;
        *(float4*)&Wsm[k][c4] = *(const float4*)(W + (size_t)k * D_MODEL + colBase + c4);
    }
    __syncthreads();

    const int rbase = warp * 16;
    float acc[8][4];
#pragma unroll
    for (int nt = 0; nt < 8; nt++)
#pragma unroll
        for (int j = 0; j < 4; j++) acc[nt][j] = 0.f;

#pragma unroll
    for (int kk = 0; kk < 4; kk++) {
        unsigned a[4];
        a[0] = f2tf(Ts[rbase + g][kk * 8 + tq]);
        a[1] = f2tf(Ts[rbase + g + 8][kk * 8 + tq]);
        a[2] = f2tf(Ts[rbase + g][kk * 8 + tq + 4]);
        a[3] = f2tf(Ts[rbase + g + 8][kk * 8 + tq + 4]);
#pragma unroll
        for (int nt = 0; nt < 8; nt++) {
            unsigned b0 = f2tf(Wsm[kk * 8 + tq][nt * 8 + g]);
            unsigned b1 = f2tf(Wsm[kk * 8 + tq + 4][nt * 8 + g]);
            mma_tf32(acc[nt], a, b0, b1);
        }
    }

#pragma unroll
    for (int nt = 0; nt < 8; nt++) {
        int col = colBase + nt * 8 + 2 * tq;
        *(float2*)(C + (size_t)(rowBase + rbase + g) * D_MODEL + col) =
            make_float2(acc[nt][0], acc[nt][1]);
        *(float2*)(C + (size_t)(rowBase + rbase + g + 8) * D_MODEL + col) =
            make_float2(acc[nt][2], acc[nt][3]);
    }
}

// -------- adapters (up to 3 projections per block, sharing the x load) -------
struct AdpArgs {
    const float* ri[3];
    const float* ro[3];
    const float* lg[3];
    float*       base[3];
    __half*      hb[3];
    int nproj;
    int ropemask;
    int hmask;       // projections whose output goes to fp16 buffer (no fp32 write)
};

__global__ void __launch_bounds__(128)
adapter_kernel(const float* __restrict__ X, const int* __restrict__ rules,
               const float2* __restrict__ rope, AdpArgs A) {
    __shared__ float xs[D_MODEL];
    __shared__ float ris[HD * RANK];
    __shared__ float ros[RANK * HD];
    __shared__ float hs[NBLK * RANK];
    __shared__ float sels[NBLK];
    int n = blockIdx.x;
    int t = threadIdx.x;
    int rule = rules[n];

    const float4* x4 = (const float4*)(X + (size_t)n * D_MODEL);
    float4* xs4 = (float4*)xs;
    xs4[t] = x4[t];
    xs4[t + 128] = x4[t + 128];

    int spos = n & (S_LEN - 1);
    int d0 = t * 8;
    int dh0 = d0 & 63;
    int blk = t >> 3;

    for (int p = 0; p < A.nproj; p++) {
#pragma unroll
        for (int i = 0; i < 4; i++) {
            ris[t + i * 128] = A.ri[p][rule * 512 + t + i * 128];
            ros[t + i * 128] = A.ro[p][rule * 512 + t + i * 128];
        }
        if (t < 32) {
            int j = t & 15;
            float v = A.lg[p][rule * NBLK + j] * 4.0f;
            float mx = v;
#pragma unroll
            for (int msk = 8; msk >= 1; msk >>= 1)
                mx = fmaxf(mx, __shfl_xor_sync(0xffffffffu, mx, msk));
            float e = expf(v - mx);
            float sm2 = e;
#pragma unroll
            for (int msk = 8; msk >= 1; msk >>= 1)
                sm2 += __shfl_xor_sync(0xffffffffu, sm2, msk);
            if (t < 16) sels[t] = e / sm2;
        }
        __syncthreads();
        {
            int bb = t >> 3, r = t & 7;
            float sum = 0.f;
#pragma unroll
            for (int sx = 0; sx < 64; sx++) sum += xs[bb * 64 + sx] * ris[sx * 8 + r];
            hs[t] = sum;
        }
        __syncthreads();
        float hl[8];
#pragma unroll
        for (int r = 0; r < 8; r++) hl[r] = hs[blk * 8 + r];
        float selv = sels[blk];
        float* Base = A.base[p];
        float4 b0 = *(float4*)(Base + (size_t)n * D_MODEL + d0);
        float4 b1 = *(float4*)(Base + (size_t)n * D_MODEL + d0 + 4);
        float outv[8] = {b0.x, b0.y, b0.z, b0.w, b1.x, b1.y, b1.z, b1.w};
        float av[8] = {0.f, 0.f, 0.f, 0.f, 0.f, 0.f, 0.f, 0.f};
#pragma unroll
        for (int r = 0; r < 8; r++) {
            float4 r0 = *(float4*)&ros[r * 64 + dh0];
            float4 r1 = *(float4*)&ros[r * 64 + dh0 + 4];
            av[0] += hl[r] * r0.x; av[1] += hl[r] * r0.y;
            av[2] += hl[r] * r0.z; av[3] += hl[r] * r0.w;
            av[4] += hl[r] * r1.x; av[5] += hl[r] * r1.y;
            av[6] += hl[r] * r1.z; av[7] += hl[r] * r1.w;
        }
#pragma unroll
        for (int c = 0; c < 8; c++) outv[c] += av[c] * selv;
        if ((A.ropemask >> p) & 1) {
#pragma unroll
            for (int pp = 0; pp < 4; pp++) {
                int i = (dh0 + 2 * pp) >> 1;
                float2 cs = __ldg(&rope[spos * 32 + i]);
                float t1 = outv[2 * pp], t2 = outv[2 * pp + 1];
                outv[2 * pp]     = t1 * cs.x - t2 * cs.y;
                outv[2 * pp + 1] = t2 * cs.x + t1 * cs.y;
            }
        }
        if ((A.hmask >> p) & 1) {
            __half* H = A.hb[p] + (size_t)n * D_MODEL + d0;
#pragma unroll
            for (int c = 0; c < 8; c += 2)
                *(__half2*)(H + c) = __floats2half2_rn(outv[c], outv[c + 1]);
        } else {
            *(float4*)(Base + (size_t)n * D_MODEL + d0)     = make_float4(outv[0], outv[1], outv[2], outv[3]);
            *(float4*)(Base + (size_t)n * D_MODEL + d0 + 4) = make_float4(outv[4], outv[5], outv[6], outv[7]);
        }
        __syncthreads();
    }
}

// ------------------------- flash attention (fp16 MMA) ------------------------
#define KV_STR 72
#define FLASH_SMEM (4 * 64 * KV_STR * 2 + 2 * 64 * 4)

__global__ void __launch_bounds__(128)
flash_tc(const __half* __restrict__ Q, const __half* __restrict__ K,
         const __half* __restrict__ V, const int* __restrict__ rules,
         const unsigned long long* __restrict__ allow, float* __restrict__ O) {
    extern __shared__ __half smh[];
    __half* ksb[2]; __half* vsb[2]; int* rkb[2];
    ksb[0] = smh;
    ksb[1] = ksb[0] + 64 * KV_STR;
    vsb[0] = ksb[1] + 64 * KV_STR;
    vsb[1] = vsb[0] + 64 * KV_STR;
    rkb[0] = (int*)(vsb[1] + 64 * KV_STR);
    rkb[1] = rkb[0] + 64;

    const int tid  = threadIdx.x;
    const int lane = tid & 31;
    const int warp = tid >> 5;
    const int g = lane >> 2, tq = lane & 3;
    const int qt = gridDim.x - 1 - blockIdx.x;     // heavy blocks first
    const int b = blockIdx.y >> 4, h = blockIdx.y & 15;
    const int tokBase = b * S_LEN;
    const int rbase = warp * 16;

    auto load_tile = [&](int buf, int kt) {
        __half* ks = ksb[buf]; __half* vs = vsb[buf];
#pragma unroll
        for (int i = 0; i < 4; i++) {
            int f = tid + i * 128;
            int key = f >> 3, ch = f & 7;
            size_t go = (size_t)(tokBase + kt * 64 + key) * D_MODEL + h * 64 + ch * 8;
            cp16(ks + key * KV_STR + ch * 8, K + go);
            cp16(vs + key * KV_STR + ch * 8, V + go);
        }
    };

    load_tile(0, 0);
    cp_commit();
    if (tid < 64) rkb[0][tid] = rules[tokBase + tid];

    const int qrow0 = qt * 64 + rbase + g;
    const int qrow1 = qrow0 + 8;

    // ---- Q A-fragments direct from gmem (fp16, packed pairs) ----
    unsigned qa[4][4];
    {
        const __half* Qr0 = Q + (size_t)(tokBase + qrow0) * D_MODEL + h * 64;
        const __half* Qr1 = Q + (size_t)(tokBase + qrow1) * D_MODEL + h * 64;
#pragma unroll
        for (int kk = 0; kk < 4; kk++) {
            qa[kk][0] = *(const unsigned*)(Qr0 + kk * 16 + 2 * tq);
            qa[kk][1] = *(const unsigned*)(Qr1 + kk * 16 + 2 * tq);
            qa[kk][2] = *(const unsigned*)(Qr0 + kk * 16 + 2 * tq + 8);
            qa[kk][3] = *(const unsigned*)(Qr1 + kk * 16 + 2 * tq + 8);
        }
    }

    const unsigned long long al0 = allow[b * S_LEN + qrow0];
    const unsigned long long al1 = allow[b * S_LEN + qrow1];

    float o[8][4];
#pragma unroll
    for (int nt = 0; nt < 8; nt++)
#pragma unroll
        for (int j = 0; j < 4; j++) o[nt][j] = 0.f;
    float m0 = NEGINF, m1 = NEGINF, l0 = 0.f, l1 = 0.f;

    for (int kt = 0; kt <= qt; kt++) {
        const int buf = kt & 1;
        __syncthreads();
        if (kt < qt) {
            load_tile(buf ^ 1, kt + 1);
            cp_commit();
            if (tid < 64) rkb[buf ^ 1][tid] = rules[tokBase + (kt + 1) * 64 + tid];
            cp_wait<1>();
        } else {
            cp_wait<0>();
        }
        __syncthreads();

        const __half* ks = ksb[buf];
        const __half* vs = vsb[buf];
        const int*    rk_s = rkb[buf];

        // ---- S = Q K^T (fp16 m16n8k16) ----
        float s[8][4];
#pragma unroll
        for (int nt = 0; nt < 8; nt++)
#pragma unroll
            for (int j = 0; j < 4; j++) s[nt][j] = 0.f;
#pragma unroll
        for (int kk = 0; kk < 4; kk++) {
#pragma unroll
            for (int nt = 0; nt < 8; nt++) {
                const __half* kp = ks + (nt * 8 + g) * KV_STR + kk * 16 + 2 * tq;
                unsigned b0 = *(const unsigned*)kp;
                unsigned b1 = *(const unsigned*)(kp + 8);
                mma_f16(s[nt], qa[kk], b0, b1);
            }
        }

        // ---- mask + scale ----
        const bool diag = (kt == qt);
#pragma unroll
        for (int nt = 0; nt < 8; nt++) {
            int c0 = nt * 8 + 2 * tq;
            int rk0 = rk_s[c0], rk1 = rk_s[c0 + 1];
            int col0 = kt * 64 + c0;
            bool ok00 = ((al0 >> rk0) & 1ULL) && (!diag || col0 <= qrow0);
            bool ok01 = ((al0 >> rk1) & 1ULL) && (!diag || col0 + 1 <= qrow0);
            bool ok10 = ((al1 >> rk0) & 1ULL) && (!diag || col0 <= qrow1);
            bool ok11 = ((al1 >> rk1) & 1ULL) && (!diag || col0 + 1 <= qrow1);
            s[nt][0] = ok00 ? s[nt][0] * 0.125f : NEGINF;
            s[nt][1] = ok01 ? s[nt][1] * 0.125f : NEGINF;
            s[nt][2] = ok10 ? s[nt][2] * 0.125f : NEGINF;
            s[nt][3] = ok11 ? s[nt][3] * 0.125f : NEGINF;
        }

        // ---- online softmax ----
        float mx0 = NEGINF, mx1 = NEGINF;
#pragma unroll
        for (int nt = 0; nt < 8; nt++) {
            mx0 = fmaxf(mx0, fmaxf(s[nt][0], s[nt][1]));
            mx1 = fmaxf(mx1, fmaxf(s[nt][2], s[nt][3]));
        }
        mx0 = fmaxf(mx0, __shfl_xor_sync(0xffffffffu, mx0, 1));
        mx0 = fmaxf(mx0, __shfl_xor_sync(0xffffffffu, mx0, 2));
        mx1 = fmaxf(mx1, __shfl_xor_sync(0xffffffffu, mx1, 1));
        mx1 = fmaxf(mx1, __shfl_xor_sync(0xffffffffu, mx1, 2));
        float mn0 = fmaxf(m0, mx0), mn1 = fmaxf(m1, mx1);
        float cr0 = (m0 == mn0) ? 1.f : __expf(m0 - mn0);
        float cr1 = (m1 == mn1) ? 1.f : __expf(m1 - mn1);
        float rs0 = 0.f, rs1 = 0.f;
        if (mn0 != NEGINF) {
#pragma unroll
            for (int nt = 0; nt < 8; nt++) {
                s[nt][0] = __expf(s[nt][0] - mn0);
                s[nt][1] = __expf(s[nt][1] - mn0);
                rs0 += s[nt][0] + s[nt][1];
            }
        } else {
#pragma unroll
            for (int nt = 0; nt < 8; nt++) { s[nt][0] = 0.f; s[nt][1] = 0.f; }
        }
        if (mn1 != NEGINF) {
#pragma unroll
            for (int nt = 0; nt < 8; nt++) {
                s[nt][2] = __expf(s[nt][2] - mn1);
                s[nt][3] = __expf(s[nt][3] - mn1);
                rs1 += s[nt][2] + s[nt][3];
            }
        } else {
#pragma unroll
            for (int nt = 0; nt < 8; nt++) { s[nt][2] = 0.f; s[nt][3] = 0.f; }
        }
        rs0 += __shfl_xor_sync(0xffffffffu, rs0, 1);
        rs0 += __shfl_xor_sync(0xffffffffu, rs0, 2);
        rs1 += __shfl_xor_sync(0xffffffffu, rs1, 1);
        rs1 += __shfl_xor_sync(0xffffffffu, rs1, 2);
        l0 = l0 * cr0 + rs0;
        l1 = l1 * cr1 + rs1;
        m0 = mn0; m1 = mn1;
#pragma unroll
        for (int nt = 0; nt < 8; nt++) {
            o[nt][0] *= cr0; o[nt][1] *= cr0;
            o[nt][2] *= cr1; o[nt][3] *= cr1;
        }

        // ---- O += P V : P packs straight from S accumulators (fp16 A layout) ----
#pragma unroll
        for (int kk = 0; kk < 4; kk++) {
            unsigned pa[4];
            pa[0] = packh2(s[2 * kk][0],     s[2 * kk][1]);
            pa[1] = packh2(s[2 * kk][2],     s[2 * kk][3]);
            pa[2] = packh2(s[2 * kk + 1][0], s[2 * kk + 1][1]);
            pa[3] = packh2(s[2 * kk + 1][2], s[2 * kk + 1][3]);
#pragma unroll
            for (int ntp = 0; ntp < 4; ntp++) {
                int mtx = lane >> 3;
                int key = kk * 16 + (mtx & 1) * 8 + (lane & 7);
                int d   = ntp * 16 + (mtx >> 1) * 8;
                unsigned r[4];
                ldsm_x4_trans(r, vs + key * KV_STR + d);
                mma_f16(o[2 * ntp],     pa, r[0], r[1]);
                mma_f16(o[2 * ntp + 1], pa, r[2], r[3]);
            }
        }
    }

    float inv0 = 1.f / l0, inv1 = 1.f / l1;
#pragma unroll
    for (int nt = 0; nt < 8; nt++) {
        float2 w0 = make_float2(o[nt][0] * inv0, o[nt][1] * inv0);
        float2 w1 = make_float2(o[nt][2] * inv1, o[nt][3] * inv1);
        *(float2*)(O + (size_t)(tokBase + qrow0) * D_MODEL + h * 64 + nt * 8 + 2 * tq) = w0;
        *(float2*)(O + (size_t)(tokBase + qrow1) * D_MODEL + h * 64 + nt * 8 + 2 * tq) = w1;
    }
}

// ----------------------------------------------------------------------------
extern "C" void kernel_launch(void* const* d_in, const int* in_sizes, int n_in,
                              void* d_out, int out_size) {
    const float* x     = (const float*)d_in[0];
    const int*   rules = (const int*)  d_in[1];
    const float* q_si = (const float*)d_in[2],  *q_so = (const float*)d_in[3];
    const float* q_ri = (const float*)d_in[4],  *q_ro = (const float*)d_in[5];
    const float* q_lg = (const float*)d_in[6];
    const float* k_si = (const float*)d_in[7],  *k_so = (const float*)d_in[8];
    const float* k_ri = (const float*)d_in[9],  *k_ro = (const float*)d_in[10];
    const float* k_lg = (const float*)d_in[11];
    const float* v_si = (const float*)d_in[12], *v_so = (const float*)d_in[13];
    const float* v_ri = (const float*)d_in[14], *v_ro = (const float*)d_in[15];
    const float* v_lg = (const float*)d_in[16];
    const float* o_si = (const float*)d_in[17], *o_so = (const float*)d_in[18];
    const float* o_ri = (const float*)d_in[19], *o_ro = (const float*)d_in[20];
    const float* o_lg = (const float*)d_in[21];
    const float* router_q = (const float*)d_in[22];
    const float* router_k = (const float*)d_in[23];
    float* out = (float*)d_out;

    float *T1, *Pp, *Qb, *Kb, *Vb, *AO, *Atab;
    __half *Qh, *Kh, *Vh;
    float2* Rope;
    unsigned long long* Allow;
    cudaGetSymbolAddress((void**)&T1,    g_T1);
    cudaGetSymbolAddress((void**)&Pp,    g_P);
    cudaGetSymbolAddress((void**)&Qb,    g_Q);
    cudaGetSymbolAddress((void**)&Kb,    g_K);
    cudaGetSymbolAddress((void**)&Vb,    g_V);
    cudaGetSymbolAddress((void**)&Qh,    g_Qh);
    cudaGetSymbolAddress((void**)&Kh,    g_Kh);
    cudaGetSymbolAddress((void**)&Vh,    g_Vh);
    cudaGetSymbolAddress((void**)&AO,    g_AO);
    cudaGetSymbolAddress((void**)&Atab,  g_A);
    cudaGetSymbolAddress((void**)&Allow, g_allow);
    cudaGetSymbolAddress((void**)&Rope,  g_rope);

    aff_kernel<<<16, 256>>>(router_q, router_k, Atab);
    rope_kernel<<<64, 512>>>(Rope);
    thr_allow_kernel<<<NTOK, 64>>>(rules, Atab, Allow);

    // QKV base projections (tf32 MMA, merged z, split-K; reduce fused in gemm2)
    cudaFuncSetAttribute(gemm1_tc<3>, cudaFuncAttributeMaxDynamicSharedMemorySize, G1_SMEM);
    cudaFuncSetAttribute(gemm1_tc<1>, cudaFuncAttributeMaxDynamicSharedMemorySize, G1_SMEM);
    gemm1_tc<3><<<dim3(32, KSPLIT), 128, G1_SMEM>>>(x, q_si, k_si, v_si, Pp);
    gemm2_tc<<<dim3(64, 16, 3), 128>>>(Pp, q_so, k_so, v_so, Qb, Kb, Vb);

    AdpArgs aq;
    aq.ri[0] = q_ri; aq.ri[1] = k_ri; aq.ri[2] = v_ri;
    aq.ro[0] = q_ro; aq.ro[1] = k_ro; aq.ro[2] = v_ro;
    aq.lg[0] = q_lg; aq.lg[1] = k_lg; aq.lg[2] = v_lg;
    aq.base[0] = Qb; aq.base[1] = Kb; aq.base[2] = Vb;
    aq.hb[0] = Qh;  aq.hb[1] = Kh;  aq.hb[2] = Vh;
    aq.nproj = 3; aq.ropemask = 0x3; aq.hmask = 0x7;
    adapter_kernel<<<NTOK, 128>>>(x, rules, Rope, aq);

    // flash attention (fp16 tensor cores, 64-row q-tiles, cp.async)
    cudaFuncSetAttribute(flash_tc, cudaFuncAttributeMaxDynamicSharedMemorySize, FLASH_SMEM);
    flash_tc<<<dim3(16, 64), 128, FLASH_SMEM>>>(Qh, Kh, Vh, rules, Allow, AO);

    // O projection
    gemm1_tc<1><<<dim3(32, KSPLIT), 128, G1_SMEM>>>(AO, o_si, o_si, o_si, Pp);
    gemm2_tc<<<dim3(64, 16, 1), 128>>>(Pp, o_so, o_so, o_so, out, out, out);

    AdpArgs ao;
    ao.ri[0] = o_ri; ao.ri[1] = o_ri; ao.ri[2] = o_ri;
    ao.ro[0] = o_ro; ao.ro[1] = o_ro; ao.ro[2] = o_ro;
    ao.lg[0] = o_lg; ao.lg[1] = o_lg; ao.lg[2] = o_lg;
    ao.base[0] = out; ao.base[1] = out; ao.base[2] = out;
    ao.hb[0] = 0; ao.hb[1] = 0; ao.hb[2] = 0;
    ao.nproj = 1; ao.ropemask = 0; ao.hmask = 0;
    adapter_kernel<<<NTOK, 128>>>(AO, rules, Rope, ao);
}